// round 14
// baseline (speedup 1.0000x reference)
#include <cuda_runtime.h>
#include <math.h>

#define KPAD   320        // >= Kv (297 for box=20, dl=4), multiple of 32
#define BMAX   8
#define NMAX   2048
#define NSPLIT 16
#define KITER  (KPAD/32)  // 10

// ---------------- scratch (zero-initialized device globals) ----------------
__device__ int    g_Kv[BMAX];
__device__ int4   g_kint[BMAX][KPAD];
__device__ float2 g_tab[BMAX][NMAX][18];       // phasor tables (cos,sin)[axis*6+m]
__device__ float  g_part[NSPLIT][4][BMAX][KPAD][64];
__device__ float  g_kpotT[2][BMAX][64][KPAD];  // k_pot re/im, [d][k] transposed
__device__ float  g_vpot[2][BMAX][KPAD][64];   // v_pot re/im, [k][d]
__device__ float  g_QT[BMAX][64][NMAX];        // Q transposed [d][n]
__device__ float  g_L[BMAX][NMAX][KPAD];       // attention logits

// ---------------- packed f32x2 helpers (Blackwell FFMA2) --------------------
__device__ __forceinline__ unsigned long long pk2(float lo, float hi) {
    unsigned long long r;
    asm("mov.b64 %0, {%1, %2};" : "=l"(r) : "f"(lo), "f"(hi));
    return r;
}
__device__ __forceinline__ void fma2(unsigned long long& d,
                                     unsigned long long a, unsigned long long b) {
    asm("fma.rn.f32x2 %0, %1, %2, %0;" : "+l"(d) : "l"(a), "l"(b));
}
__device__ __forceinline__ float2 up2(unsigned long long v) {
    float2 f;
    asm("mov.b64 {%0, %1}, %2;" : "=f"(f.x), "=f"(f.y) : "l"(v));
    return f;
}

// ---------------- cp.async helpers ------------------------------------------
__device__ __forceinline__ void cpa16(void* smem, const void* gmem) {
    unsigned int sa = (unsigned int)__cvta_generic_to_shared(smem);
    asm volatile("cp.async.ca.shared.global [%0], [%1], 16;" :: "r"(sa), "l"(gmem));
}
#define CPA_COMMIT() asm volatile("cp.async.commit_group;" ::: "memory")
#define CPA_WAIT0()  asm volatile("cp.async.wait_group 0;" ::: "memory")

// ---------------- K0: valid k-list, warp-parallel ordered compaction -------
// Bit-exact emulation of reference validity (no FFMA contraction; the 21
// boundary points with |k|^2 == 25 must be INCLUDED).
__global__ void k_build(const float* __restrict__ cell)
{
    int b = blockIdx.x;
    int lane = threadIdx.x;
    float bx = cell[b*9 + 0];
    float by = cell[b*9 + 4];
    float bz = cell[b*9 + 8];
    int nkx = max(1, (int)(bx / 4.0f));
    int nky = max(1, (int)(by / 4.0f));
    int nkz = max(1, (int)(bz / 4.0f));
    const float TWOPI_SQ = 39.47841760435743f;   // (2*pi)^2
    const float KSQMAX   = 2.4674011002723395f;  // (2*pi/4)^2
    int ny = 2*nky + 1, nz = 2*nkz + 1;
    int total = (nkx + 1) * ny * nz;
    int cnt = 0;
    for (int base = 0; base < total; base += 32) {
        int idx = base + lane;
        bool valid = false;
        int kx = 0, ky = 0, kz = 0;
        if (idx < total) {
            kx = idx / (ny * nz);
            int r = idx % (ny * nz);
            ky = r / nz - nky;
            kz = r % nz - nkz;
            float fx = __fdiv_rn((float)kx, bx);
            float fy = __fdiv_rn((float)ky, by);
            float fz = __fdiv_rn((float)kz, bz);
            float sx = __fmul_rn(fx, fx);
            float sy = __fmul_rn(fy, fy);
            float sz = __fmul_rn(fz, fz);
            float s  = __fadd_rn(__fadd_rn(sx, sy), sz);
            float ksq = __fmul_rn(TWOPI_SQ, s);
            valid = (ksq <= KSQMAX) && (ksq > 0.0f);
        }
        unsigned m = __ballot_sync(0xffffffffu, valid);
        int pos = cnt + __popc(m & ((1u << lane) - 1u));
        if (valid && pos < KPAD) g_kint[b][pos] = make_int4(kx, ky, kz, 0);
        cnt += __popc(m);
    }
    if (lane == 0) g_Kv[b] = min(cnt, KPAD);
}

// ---------------- K0b: transpose Q into [d][n] -------------------------------
__global__ void k_qT(const float* __restrict__ qmat, int n)
{
    __shared__ float tile[32][33];
    int b  = blockIdx.z;
    int n0 = blockIdx.x * 32;
    int d0 = blockIdx.y * 32;
    int x = threadIdx.x, y = threadIdx.y;
    #pragma unroll
    for (int i = 0; i < 32; i += 8)
        tile[y + i][x] = qmat[((size_t)(b*n + n0 + y + i)) * 64 + d0 + x];
    __syncthreads();
    #pragma unroll
    for (int i = 0; i < 32; i += 8)
        g_QT[b][d0 + y + i][n0 + x] = tile[x][y + i];
}

// ---------------- K0c: phasor tables, computed ONCE per (b, node) ----------
__global__ void k_tab(const float* __restrict__ pos,
                      const float* __restrict__ cell, int n, int B)
{
    int idx = blockIdx.x * 256 + threadIdx.x;
    int total = B * n * 18;
    if (idx >= total) return;
    int e    = idx % 18;
    int node = (idx / 18) % n;
    int b    = idx / (18 * n);
    int a = e / 6, m = e % 6;
    float box = cell[b*9 + a*4];
    float u = pos[((size_t)(b*n + node)) * 3 + a] / box;
    float t = u * (float)m;
    t -= floorf(t);
    float sv, cv;
    sincospif(2.0f * t, &sv, &cv);
    g_tab[b][node][e] = make_float2(cv, sv);
}

// compose e^{i 2pi k.u} from a node's phasor table (float2 (cos,sin)[a*6+m])
__device__ __forceinline__ void compose_e2(const float2* tab, int4 kv,
                                           float& c, float& s)
{
    float2 ex = tab[kv.x];
    float2 ey = tab[6 + abs(kv.y)];
    float sy = (kv.y < 0) ? -ey.y : ey.y;
    float2 ez = tab[12 + abs(kv.z)];
    float sz = (kv.z < 0) ? -ez.y : ez.y;
    float c1 = ex.x*ey.x - ex.y*sy;
    float s1 = ex.x*sy + ex.y*ey.x;
    c = c1*ez.x - s1*sz;
    s = c1*sz + s1*ez.x;
}

// ---------------- K2: k_pot/v_pot partials — 32k x 64d CTA tile -------------
// warp-uniform E fragments (LDS broadcast), 32 acc regs, cp.async pipeline.
// launch_bounds(256,4): 64-reg cap -> 4 CTAs/SM (accs stay resident; only
// cold prologue values may spill).
__global__ void __launch_bounds__(256, 4) k_pot(const float* __restrict__ kmat,
                                                const float* __restrict__ vmat,
                                                int n)
{
    int b  = blockIdx.z;
    int Kv = g_Kv[b];
    int k0 = blockIdx.x * 32;
    int nper = n / NSPLIT;          // 128
    int n0 = blockIdx.y * nper;
    int t  = threadIdx.x;
    int tk   = t >> 5;              // warp id 0..7 -> k base tk*4
    int lane = t & 31;              // d pair: d = lane*2

    __shared__ float2 stab[128][18];                 // 18 KB (nper nodes)
    __shared__ float  sEc[2][16][32], sEs[2][16][32];// 8 KB
    __shared__ float  sK[2][16][64],  sV[2][16][64]; // 16 KB
    __shared__ int4   skint[32];

    {
        const float2* src = &g_tab[b][n0][0];
        float2* dst = &stab[0][0];
        for (int i = t; i < 128 * 18; i += 256) dst[i] = src[i];
    }
    if (t < 32) skint[t] = g_kint[b][k0 + t];

    int lnode = t >> 4, ldq = t & 15;   // tile loader mapping (16 nodes x 16 f4)
    const float4* kp = (const float4*)kmat + (size_t)(b*n + n0 + lnode) * 16 + ldq;
    const float4* vp = (const float4*)vmat + (size_t)(b*n + n0 + lnode) * 16 + ldq;

    unsigned long long akr[2][2] = {}, aki[2][2] = {}, avr[2][2] = {}, avi[2][2] = {};

    // prologue: cp.async chunk 0 -> buf 0
    cpa16(&sK[0][lnode][ldq*4], kp);
    cpa16(&sV[0][lnode][ldq*4], vp);
    CPA_COMMIT();
    __syncthreads();                       // stab/skint visible
    // compose chunk 0 -> sEc[0]
    #pragma unroll
    for (int r = 0; r < 2; r++) {
        int fid = t + r * 256;
        int nn = fid >> 5, kx = fid & 31;
        float c, s;
        compose_e2(&stab[nn][0], skint[kx], c, s);
        sEc[0][nn][kx] = c;
        sEs[0][nn][kx] = s;
    }
    CPA_WAIT0();
    __syncthreads();

    const int nchunks = nper / 16;         // 8
    for (int ic = 0; ic < nchunks; ic++) {
        int c = ic & 1;
        if (ic + 1 < nchunks) {            // async-load next chunk into alt buffer
            cpa16(&sK[1-c][lnode][ldq*4], kp + (ic + 1) * 256);
            cpa16(&sV[1-c][lnode][ldq*4], vp + (ic + 1) * 256);
            CPA_COMMIT();
        }
        #pragma unroll
        for (int nn = 0; nn < 16; nn++) {
            float4 ec4 = *(const float4*)&sEc[c][nn][tk*4];   // warp-uniform (bcast)
            float4 es4 = *(const float4*)&sEs[c][nn][tk*4];
            float2 xk2 = *(const float2*)&sK[c][nn][lane*2];
            float2 xv2 = *(const float2*)&sV[c][nn][lane*2];
            unsigned long long ecp0 = pk2(ec4.x, ec4.y), ecp1 = pk2(ec4.z, ec4.w);
            unsigned long long esp0 = pk2(es4.x, es4.y), esp1 = pk2(es4.z, es4.w);
            unsigned long long bk0 = pk2(xk2.x, xk2.x), bk1 = pk2(xk2.y, xk2.y);
            unsigned long long bv0 = pk2(xv2.x, xv2.x), bv1 = pk2(xv2.y, xv2.y);
            fma2(akr[0][0], ecp0, bk0); fma2(akr[0][1], ecp0, bk1);
            fma2(akr[1][0], ecp1, bk0); fma2(akr[1][1], ecp1, bk1);
            fma2(aki[0][0], esp0, bk0); fma2(aki[0][1], esp0, bk1);
            fma2(aki[1][0], esp1, bk0); fma2(aki[1][1], esp1, bk1);
            fma2(avr[0][0], ecp0, bv0); fma2(avr[0][1], ecp0, bv1);
            fma2(avr[1][0], ecp1, bv0); fma2(avr[1][1], ecp1, bv1);
            fma2(avi[0][0], esp0, bv0); fma2(avi[0][1], esp0, bv1);
            fma2(avi[1][0], esp1, bv0); fma2(avi[1][1], esp1, bv1);
        }
        if (ic + 1 < nchunks) {            // compose next chunk's E into alt buffer
            #pragma unroll
            for (int r = 0; r < 2; r++) {
                int fid = t + r * 256;
                int nn = fid >> 5, kx = fid & 31;
                float cc, ss;
                compose_e2(&stab[(ic + 1) * 16 + nn][0], skint[kx], cc, ss);
                sEc[1-c][nn][kx] = cc;
                sEs[1-c][nn][kx] = ss;
            }
            CPA_WAIT0();
        }
        __syncthreads();
    }

    // epilogue: [p][j] -> k = k0 + tk*4 + 2p (+1 via pair), d = lane*2 + j
    int s = blockIdx.y;
    #pragma unroll
    for (int p = 0; p < 2; p++) {
        float2 r0 = up2(akr[p][0]), r1 = up2(akr[p][1]);
        float2 i0 = up2(aki[p][0]), i1 = up2(aki[p][1]);
        float2 v0 = up2(avr[p][0]), v1 = up2(avr[p][1]);
        float2 w0 = up2(avi[p][0]), w1 = up2(avi[p][1]);
        int kkA = k0 + tk*4 + p*2;
        int kkB = kkA + 1;
        if (kkA < Kv) {
            *(float2*)&g_part[s][0][b][kkA][lane*2] = make_float2(r0.x, r1.x);
            *(float2*)&g_part[s][1][b][kkA][lane*2] = make_float2(i0.x, i1.x);
            *(float2*)&g_part[s][2][b][kkA][lane*2] = make_float2(v0.x, v1.x);
            *(float2*)&g_part[s][3][b][kkA][lane*2] = make_float2(w0.x, w1.x);
        }
        if (kkB < Kv) {
            *(float2*)&g_part[s][0][b][kkB][lane*2] = make_float2(r0.y, r1.y);
            *(float2*)&g_part[s][1][b][kkB][lane*2] = make_float2(i0.y, i1.y);
            *(float2*)&g_part[s][2][b][kkB][lane*2] = make_float2(v0.y, v1.y);
            *(float2*)&g_part[s][3][b][kkB][lane*2] = make_float2(w0.y, w1.y);
        }
    }
}

// ---------------- K2b: deterministic split reduction -----------------------
__global__ void k_reduce(int B)
{
    int idx = blockIdx.x * 256 + threadIdx.x;
    int total = 4 * B * KPAD * 64;
    if (idx >= total) return;
    int d  = idx & 63;
    int k  = (idx >> 6) % KPAD;
    int rb = (idx >> 6) / KPAD;
    int b  = rb % B;
    int m  = rb / B;
    if (k >= g_Kv[b]) return;
    float s = 0.f;
    #pragma unroll
    for (int sp = 0; sp < NSPLIT; sp++) s += g_part[sp][m][b][k][d];
    if (m < 2) g_kpotT[m][b][d][k] = s;
    else       g_vpot[m - 2][b][k][d] = s;
}

// ---------------- K3: logits L = Re(e * (Q @ kpot^T)) — fused compose ------
__global__ void __launch_bounds__(128) k_z(int n)
{
    int b  = blockIdx.z;
    int k0 = blockIdx.x * 64;
    int n0 = blockIdx.y * 64;
    int t  = threadIdx.x;
    int tk = t & 15;                // 16 groups x 4k
    int tn = t >> 4;                // 8 groups x 8n

    __shared__ float  sQT[64][64];   // [d][node]
    __shared__ float  sKR[64][64];   // [d][k]
    __shared__ float  sKI[64][64];   // [d][k]
    __shared__ float2 stab[64][18];
    __shared__ int4   skint[64];

    #pragma unroll
    for (int r = 0; r < 8; r++) {
        int fid = t + r * 128;
        int d = fid >> 4, nq = fid & 15;
        *(float4*)&sQT[d][nq*4] = *(const float4*)&g_QT[b][d][n0 + nq*4];
    }
    #pragma unroll
    for (int r = 0; r < 8; r++) {
        int fid = t + r * 128;
        int d = fid >> 4, kq = fid & 15;
        *(float4*)&sKR[d][kq*4] = *(const float4*)&g_kpotT[0][b][d][k0 + kq*4];
        *(float4*)&sKI[d][kq*4] = *(const float4*)&g_kpotT[1][b][d][k0 + kq*4];
    }
    {
        const float2* src = &g_tab[b][n0][0];
        float2* dst = &stab[0][0];
        for (int i = t; i < 64 * 18; i += 128) dst[i] = src[i];
    }
    if (t < 64) skint[t] = g_kint[b][k0 + t];

    unsigned long long zr2[4][4] = {}, zi2[4][4] = {};  // [n-pair][k j]
    __syncthreads();

    #pragma unroll 4
    for (int dd = 0; dd < 64; dd++) {
        float4 a0 = *(const float4*)&sQT[dd][tn*8];
        float4 a1 = *(const float4*)&sQT[dd][tn*8 + 4];
        float4 br = *(const float4*)&sKR[dd][tk*4];
        float4 bi = *(const float4*)&sKI[dd][tk*4];
        unsigned long long ap[4] = { pk2(a0.x, a0.y), pk2(a0.z, a0.w),
                                     pk2(a1.x, a1.y), pk2(a1.z, a1.w) };
        float brr[4] = {br.x, br.y, br.z, br.w};
        float bii[4] = {bi.x, bi.y, bi.z, bi.w};
        #pragma unroll
        for (int j = 0; j < 4; j++) {
            unsigned long long bb = pk2(brr[j], brr[j]);
            unsigned long long cc = pk2(bii[j], bii[j]);
            #pragma unroll
            for (int p = 0; p < 4; p++) {
                fma2(zr2[p][j], ap[p], bb);
                fma2(zi2[p][j], ap[p], cc);
            }
        }
    }

    int kbase = tk * 4;
    #pragma unroll
    for (int p = 0; p < 4; p++) {
        int nA = tn*8 + p*2;
        int nB = nA + 1;
        float4 LA, LB;
        #pragma unroll
        for (int j = 0; j < 4; j++) {
            float2 zr = up2(zr2[p][j]);
            float2 zi = up2(zi2[p][j]);
            float ec, es;
            compose_e2(&stab[nA][0], skint[kbase + j], ec, es);
            (&LA.x)[j] = ec * zr.x - es * zi.x;
            compose_e2(&stab[nB][0], skint[kbase + j], ec, es);
            (&LB.x)[j] = ec * zr.y - es * zi.y;
        }
        *(float4*)&g_L[b][n0 + nA][k0 + kbase] = LA;
        *(float4*)&g_L[b][n0 + nB][k0 + kbase] = LB;
    }
}

// ---------------- K5: OUT — fused softmax + pipelined GEMM ------------------
// Per-node softmax stats computed in a 2-threads-per-node prologue; p =
// exp(L - mx) * inv is formed inline during W staging (k_soft + g_P deleted).
__global__ void __launch_bounds__(128) k_out(float* __restrict__ out, int n)
{
    int b  = blockIdx.y;
    int n0 = blockIdx.x * 64;
    int Kv = g_Kv[b];
    int t  = threadIdx.x;
    int td = t & 15;                // 16 groups x 4d
    int tn = t >> 4;                // 8 groups x 8n

    __shared__ float2 stab[64][18];
    __shared__ float  sWr[2][16][68], sWi[2][16][68];  // [buf][kk][node] (+pad)
    __shared__ float  sVr[2][16][64], sVi[2][16][64];  // [buf][kk][d] (sVi negated)
    __shared__ int4   skint[KPAD];
    __shared__ float  sMx[64], sInv[64];

    {
        const float2* src = &g_tab[b][n0][0];
        float2* dst = &stab[0][0];
        for (int i = t; i < 64 * 18; i += 128) dst[i] = src[i];
    }
    for (int i = t; i < KPAD; i += 128) skint[i] = g_kint[b][i];

    // ---- softmax prologue: 2 threads per node over g_L row ----
    {
        int node = t >> 1, half = t & 1;
        const float4* Lr = (const float4*)&g_L[b][n0 + node][0];
        float mx = -1e30f;
        for (int i = half; i < KPAD / 4; i += 2) {
            float4 v = Lr[i];
            int kb = i * 4;
            if (kb + 0 < Kv) mx = fmaxf(mx, v.x);
            if (kb + 1 < Kv) mx = fmaxf(mx, v.y);
            if (kb + 2 < Kv) mx = fmaxf(mx, v.z);
            if (kb + 3 < Kv) mx = fmaxf(mx, v.w);
        }
        mx = fmaxf(mx, __shfl_xor_sync(0xffffffffu, mx, 1));
        float sum = 0.f;
        for (int i = half; i < KPAD / 4; i += 2) {
            float4 v = Lr[i];
            int kb = i * 4;
            if (kb + 0 < Kv) sum += __expf(v.x - mx);
            if (kb + 1 < Kv) sum += __expf(v.y - mx);
            if (kb + 2 < Kv) sum += __expf(v.z - mx);
            if (kb + 3 < Kv) sum += __expf(v.w - mx);
        }
        sum += __shfl_xor_sync(0xffffffffu, sum, 1);
        if (half == 0) {
            sMx[node]  = mx;
            sInv[node] = 1.0f / sum;
        }
    }

    unsigned long long acc2[4][4] = {};   // [n-pair][d j]

    float  pL[8];
    float4 pvr[2], pvi[2];
    __syncthreads();                      // stab/skint/sMx/sInv ready

    // prologue: prefetch chunk 0 (L values + vpot)
    #pragma unroll
    for (int r = 0; r < 8; r++) {
        int fid = t + r * 128;
        pL[r] = g_L[b][n0 + (fid >> 4)][fid & 15];
    }
    #pragma unroll
    for (int r = 0; r < 2; r++) {
        int fid = t + r * 128;
        int kk = fid >> 4, dq = fid & 15;
        pvr[r] = *(const float4*)&g_vpot[0][b][kk][dq*4];
        pvi[r] = *(const float4*)&g_vpot[1][b][kk][dq*4];
    }
    // stage chunk 0
    #pragma unroll
    for (int r = 0; r < 8; r++) {
        int fid = t + r * 128;
        int kk = fid & 15, node = fid >> 4;
        float p = (kk < Kv) ? __expf(pL[r] - sMx[node]) * sInv[node] : 0.f;
        float c, s;
        compose_e2(&stab[node][0], skint[kk], c, s);
        sWr[0][kk][node] = p * c;
        sWi[0][kk][node] = p * s;
    }
    #pragma unroll
    for (int r = 0; r < 2; r++) {
        int fid = t + r * 128;
        int kk = fid >> 4, dq = fid & 15;
        *(float4*)&sVr[0][kk][dq*4] = pvr[r];
        *(float4*)&sVi[0][kk][dq*4] = make_float4(-pvi[r].x, -pvi[r].y, -pvi[r].z, -pvi[r].w);
    }
    __syncthreads();

    const int nch = KPAD / 16;            // 20
    for (int ic = 0; ic < nch; ic++) {
        int c = ic & 1;
        if (ic + 1 < nch) {               // prefetch next chunk
            int k0n = (ic + 1) * 16;
            #pragma unroll
            for (int r = 0; r < 8; r++) {
                int fid = t + r * 128;
                pL[r] = g_L[b][n0 + (fid >> 4)][k0n + (fid & 15)];
            }
            #pragma unroll
            for (int r = 0; r < 2; r++) {
                int fid = t + r * 128;
                int kk = fid >> 4, dq = fid & 15;
                pvr[r] = *(const float4*)&g_vpot[0][b][k0n + kk][dq*4];
                pvi[r] = *(const float4*)&g_vpot[1][b][k0n + kk][dq*4];
            }
        }
        #pragma unroll 4
        for (int kk = 0; kk < 16; kk++) {
            float4 wra = *(const float4*)&sWr[c][kk][tn*8];
            float4 wrb = *(const float4*)&sWr[c][kk][tn*8 + 4];
            float4 wia = *(const float4*)&sWi[c][kk][tn*8];
            float4 wib = *(const float4*)&sWi[c][kk][tn*8 + 4];
            float4 vr4 = *(const float4*)&sVr[c][kk][td*4];
            float4 vn4 = *(const float4*)&sVi[c][kk][td*4];
            unsigned long long wp[4] = { pk2(wra.x, wra.y), pk2(wra.z, wra.w),
                                         pk2(wrb.x, wrb.y), pk2(wrb.z, wrb.w) };
            unsigned long long ip[4] = { pk2(wia.x, wia.y), pk2(wia.z, wia.w),
                                         pk2(wib.x, wib.y), pk2(wib.z, wib.w) };
            float vr[4] = {vr4.x, vr4.y, vr4.z, vr4.w};
            float vn[4] = {vn4.x, vn4.y, vn4.z, vn4.w};
            #pragma unroll
            for (int j = 0; j < 4; j++) {
                unsigned long long bb = pk2(vr[j], vr[j]);
                unsigned long long cc = pk2(vn[j], vn[j]);
                #pragma unroll
                for (int p = 0; p < 4; p++) {
                    fma2(acc2[p][j], wp[p], bb);
                    fma2(acc2[p][j], ip[p], cc);
                }
            }
        }
        if (ic + 1 < nch) {               // stage next chunk into alt buffer
            int k0n = (ic + 1) * 16;
            #pragma unroll
            for (int r = 0; r < 8; r++) {
                int fid = t + r * 128;
                int kk = fid & 15, node = fid >> 4;
                int kg = k0n + kk;
                float p = (kg < Kv) ? __expf(pL[r] - sMx[node]) * sInv[node] : 0.f;
                float cc, ss;
                compose_e2(&stab[node][0], skint[kg], cc, ss);
                sWr[1-c][kk][node] = p * cc;
                sWi[1-c][kk][node] = p * ss;
            }
            #pragma unroll
            for (int r = 0; r < 2; r++) {
                int fid = t + r * 128;
                int kk = fid >> 4, dq = fid & 15;
                *(float4*)&sVr[1-c][kk][dq*4] = pvr[r];
                *(float4*)&sVi[1-c][kk][dq*4] = make_float4(-pvi[r].x, -pvi[r].y, -pvi[r].z, -pvi[r].w);
            }
        }
        __syncthreads();
    }

    #pragma unroll
    for (int p = 0; p < 4; p++) {
        float2 a0 = up2(acc2[p][0]), a1 = up2(acc2[p][1]), a2 = up2(acc2[p][2]), a3 = up2(acc2[p][3]);
        float* opA = out + ((size_t)(b*n + n0 + tn*8 + p*2)) * 64 + td*4;
        float* opB = opA + 64;
        *(float4*)opA = make_float4(a0.x, a1.x, a2.x, a3.x);
        *(float4*)opB = make_float4(a0.y, a1.y, a2.y, a3.y);
    }
}

// ---------------- launch -----------------------------------------------------
// k_pot stays at launch #4 (the observed ncu window). 7 launches total.
extern "C" void kernel_launch(void* const* d_in, const int* in_sizes, int n_in,
                              void* d_out, int out_size)
{
    const float* q    = (const float*)d_in[0];
    const float* kmat = (const float*)d_in[1];
    const float* vmat = (const float*)d_in[2];
    const float* pos  = (const float*)d_in[3];
    const float* cell = (const float*)d_in[4];
    // d_in[5] = batch indices (contiguous equal-size graphs; unused)

    int N = in_sizes[0] / 64;
    int B = in_sizes[4] / 9;
    int n = N / B;

    k_qT<<<dim3(n / 32, 2, B), dim3(32, 8)>>>(q, n);                 // 1
    k_build<<<B, 32>>>(cell);                                        // 2
    k_tab<<<(B * n * 18 + 255) / 256, 256>>>(pos, cell, n, B);       // 3
    k_pot<<<dim3(KPAD / 32, NSPLIT, B), 256>>>(kmat, vmat, n);       // 4 (profiled)
    int total = 4 * B * KPAD * 64;
    k_reduce<<<(total + 255) / 256, 256>>>(B);                       // 5
    k_z<<<dim3(KPAD / 64, n / 64, B), 128>>>(n);                     // 6
    k_out<<<dim3(n / 64, B), 128>>>((float*)d_out, n);               // 7
}

// round 15
// speedup vs baseline: 1.0140x; 1.0140x over previous
#include <cuda_runtime.h>
#include <math.h>

#define KPAD   320        // >= Kv (297 for box=20, dl=4), multiple of 32
#define BMAX   8
#define NMAX   2048
#define NSPLIT 16
#define KITER  (KPAD/32)  // 10

// ---------------- scratch (zero-initialized device globals) ----------------
__device__ int    g_Kv[BMAX];
__device__ int4   g_kint[BMAX][KPAD];
__device__ float2 g_tab[BMAX][NMAX][18];       // phasor tables (cos,sin)[axis*6+m]
__device__ float  g_part[NSPLIT][4][BMAX][KPAD][64];
__device__ float  g_kpotT[2][BMAX][64][KPAD];  // k_pot re/im, [d][k] transposed
__device__ float  g_vpot[2][BMAX][KPAD][64];   // v_pot re/im, [k][d]
__device__ float  g_QT[BMAX][64][NMAX];        // Q transposed [d][n]
__device__ float  g_L[BMAX][NMAX][KPAD];       // attention logits
__device__ float2 g_stat[BMAX][NMAX];          // per-node softmax (max, 1/sum)

// ---------------- packed f32x2 helpers (Blackwell FFMA2) --------------------
__device__ __forceinline__ unsigned long long pk2(float lo, float hi) {
    unsigned long long r;
    asm("mov.b64 %0, {%1, %2};" : "=l"(r) : "f"(lo), "f"(hi));
    return r;
}
__device__ __forceinline__ void fma2(unsigned long long& d,
                                     unsigned long long a, unsigned long long b) {
    asm("fma.rn.f32x2 %0, %1, %2, %0;" : "+l"(d) : "l"(a), "l"(b));
}
__device__ __forceinline__ float2 up2(unsigned long long v) {
    float2 f;
    asm("mov.b64 {%0, %1}, %2;" : "=f"(f.x), "=f"(f.y) : "l"(v));
    return f;
}

// ---------------- cp.async helpers ------------------------------------------
__device__ __forceinline__ void cpa16(void* smem, const void* gmem) {
    unsigned int sa = (unsigned int)__cvta_generic_to_shared(smem);
    asm volatile("cp.async.ca.shared.global [%0], [%1], 16;" :: "r"(sa), "l"(gmem));
}
#define CPA_COMMIT() asm volatile("cp.async.commit_group;" ::: "memory")
#define CPA_WAIT0()  asm volatile("cp.async.wait_group 0;" ::: "memory")

// ---------------- K0: valid k-list, warp-parallel ordered compaction -------
// Bit-exact emulation of reference validity (no FFMA contraction; the 21
// boundary points with |k|^2 == 25 must be INCLUDED).
__global__ void k_build(const float* __restrict__ cell)
{
    int b = blockIdx.x;
    int lane = threadIdx.x;
    float bx = cell[b*9 + 0];
    float by = cell[b*9 + 4];
    float bz = cell[b*9 + 8];
    int nkx = max(1, (int)(bx / 4.0f));
    int nky = max(1, (int)(by / 4.0f));
    int nkz = max(1, (int)(bz / 4.0f));
    const float TWOPI_SQ = 39.47841760435743f;   // (2*pi)^2
    const float KSQMAX   = 2.4674011002723395f;  // (2*pi/4)^2
    int ny = 2*nky + 1, nz = 2*nkz + 1;
    int total = (nkx + 1) * ny * nz;
    int cnt = 0;
    for (int base = 0; base < total; base += 32) {
        int idx = base + lane;
        bool valid = false;
        int kx = 0, ky = 0, kz = 0;
        if (idx < total) {
            kx = idx / (ny * nz);
            int r = idx % (ny * nz);
            ky = r / nz - nky;
            kz = r % nz - nkz;
            float fx = __fdiv_rn((float)kx, bx);
            float fy = __fdiv_rn((float)ky, by);
            float fz = __fdiv_rn((float)kz, bz);
            float sx = __fmul_rn(fx, fx);
            float sy = __fmul_rn(fy, fy);
            float sz = __fmul_rn(fz, fz);
            float s  = __fadd_rn(__fadd_rn(sx, sy), sz);
            float ksq = __fmul_rn(TWOPI_SQ, s);
            valid = (ksq <= KSQMAX) && (ksq > 0.0f);
        }
        unsigned m = __ballot_sync(0xffffffffu, valid);
        int pos = cnt + __popc(m & ((1u << lane) - 1u));
        if (valid && pos < KPAD) g_kint[b][pos] = make_int4(kx, ky, kz, 0);
        cnt += __popc(m);
    }
    if (lane == 0) g_Kv[b] = min(cnt, KPAD);
}

// ---------------- K0b: transpose Q into [d][n] -------------------------------
__global__ void k_qT(const float* __restrict__ qmat, int n)
{
    __shared__ float tile[32][33];
    int b  = blockIdx.z;
    int n0 = blockIdx.x * 32;
    int d0 = blockIdx.y * 32;
    int x = threadIdx.x, y = threadIdx.y;
    #pragma unroll
    for (int i = 0; i < 32; i += 8)
        tile[y + i][x] = qmat[((size_t)(b*n + n0 + y + i)) * 64 + d0 + x];
    __syncthreads();
    #pragma unroll
    for (int i = 0; i < 32; i += 8)
        g_QT[b][d0 + y + i][n0 + x] = tile[x][y + i];
}

// ---------------- K0c: phasor tables, computed ONCE per (b, node) ----------
__global__ void k_tab(const float* __restrict__ pos,
                      const float* __restrict__ cell, int n, int B)
{
    int idx = blockIdx.x * 256 + threadIdx.x;
    int total = B * n * 18;
    if (idx >= total) return;
    int e    = idx % 18;
    int node = (idx / 18) % n;
    int b    = idx / (18 * n);
    int a = e / 6, m = e % 6;
    float box = cell[b*9 + a*4];
    float u = pos[((size_t)(b*n + node)) * 3 + a] / box;
    float t = u * (float)m;
    t -= floorf(t);
    float sv, cv;
    sincospif(2.0f * t, &sv, &cv);
    g_tab[b][node][e] = make_float2(cv, sv);
}

// compose e^{i 2pi k.u} from a node's phasor table (float2 (cos,sin)[a*6+m])
__device__ __forceinline__ void compose_e2(const float2* tab, int4 kv,
                                           float& c, float& s)
{
    float2 ex = tab[kv.x];
    float2 ey = tab[6 + abs(kv.y)];
    float sy = (kv.y < 0) ? -ey.y : ey.y;
    float2 ez = tab[12 + abs(kv.z)];
    float sz = (kv.z < 0) ? -ez.y : ez.y;
    float c1 = ex.x*ey.x - ex.y*sy;
    float s1 = ex.x*sy + ex.y*ey.x;
    c = c1*ez.x - s1*sz;
    s = c1*sz + s1*ez.x;
}

// ---------------- K2: k_pot/v_pot partials — 32k x 64d CTA tile -------------
// (unchanged from R14: regs 63, 4 CTAs/SM, 64.1us verified)
__global__ void __launch_bounds__(256, 4) k_pot(const float* __restrict__ kmat,
                                                const float* __restrict__ vmat,
                                                int n)
{
    int b  = blockIdx.z;
    int Kv = g_Kv[b];
    int k0 = blockIdx.x * 32;
    int nper = n / NSPLIT;          // 128
    int n0 = blockIdx.y * nper;
    int t  = threadIdx.x;
    int tk   = t >> 5;              // warp id 0..7 -> k base tk*4
    int lane = t & 31;              // d pair: d = lane*2

    __shared__ float2 stab[128][18];                 // 18 KB (nper nodes)
    __shared__ float  sEc[2][16][32], sEs[2][16][32];// 8 KB
    __shared__ float  sK[2][16][64],  sV[2][16][64]; // 16 KB
    __shared__ int4   skint[32];

    {
        const float2* src = &g_tab[b][n0][0];
        float2* dst = &stab[0][0];
        for (int i = t; i < 128 * 18; i += 256) dst[i] = src[i];
    }
    if (t < 32) skint[t] = g_kint[b][k0 + t];

    int lnode = t >> 4, ldq = t & 15;   // tile loader mapping (16 nodes x 16 f4)
    const float4* kp = (const float4*)kmat + (size_t)(b*n + n0 + lnode) * 16 + ldq;
    const float4* vp = (const float4*)vmat + (size_t)(b*n + n0 + lnode) * 16 + ldq;

    unsigned long long akr[2][2] = {}, aki[2][2] = {}, avr[2][2] = {}, avi[2][2] = {};

    cpa16(&sK[0][lnode][ldq*4], kp);
    cpa16(&sV[0][lnode][ldq*4], vp);
    CPA_COMMIT();
    __syncthreads();
    #pragma unroll
    for (int r = 0; r < 2; r++) {
        int fid = t + r * 256;
        int nn = fid >> 5, kx = fid & 31;
        float c, s;
        compose_e2(&stab[nn][0], skint[kx], c, s);
        sEc[0][nn][kx] = c;
        sEs[0][nn][kx] = s;
    }
    CPA_WAIT0();
    __syncthreads();

    const int nchunks = nper / 16;         // 8
    for (int ic = 0; ic < nchunks; ic++) {
        int c = ic & 1;
        if (ic + 1 < nchunks) {
            cpa16(&sK[1-c][lnode][ldq*4], kp + (ic + 1) * 256);
            cpa16(&sV[1-c][lnode][ldq*4], vp + (ic + 1) * 256);
            CPA_COMMIT();
        }
        #pragma unroll
        for (int nn = 0; nn < 16; nn++) {
            float4 ec4 = *(const float4*)&sEc[c][nn][tk*4];   // warp-uniform (bcast)
            float4 es4 = *(const float4*)&sEs[c][nn][tk*4];
            float2 xk2 = *(const float2*)&sK[c][nn][lane*2];
            float2 xv2 = *(const float2*)&sV[c][nn][lane*2];
            unsigned long long ecp0 = pk2(ec4.x, ec4.y), ecp1 = pk2(ec4.z, ec4.w);
            unsigned long long esp0 = pk2(es4.x, es4.y), esp1 = pk2(es4.z, es4.w);
            unsigned long long bk0 = pk2(xk2.x, xk2.x), bk1 = pk2(xk2.y, xk2.y);
            unsigned long long bv0 = pk2(xv2.x, xv2.x), bv1 = pk2(xv2.y, xv2.y);
            fma2(akr[0][0], ecp0, bk0); fma2(akr[0][1], ecp0, bk1);
            fma2(akr[1][0], ecp1, bk0); fma2(akr[1][1], ecp1, bk1);
            fma2(aki[0][0], esp0, bk0); fma2(aki[0][1], esp0, bk1);
            fma2(aki[1][0], esp1, bk0); fma2(aki[1][1], esp1, bk1);
            fma2(avr[0][0], ecp0, bv0); fma2(avr[0][1], ecp0, bv1);
            fma2(avr[1][0], ecp1, bv0); fma2(avr[1][1], ecp1, bv1);
            fma2(avi[0][0], esp0, bv0); fma2(avi[0][1], esp0, bv1);
            fma2(avi[1][0], esp1, bv0); fma2(avi[1][1], esp1, bv1);
        }
        if (ic + 1 < nchunks) {
            #pragma unroll
            for (int r = 0; r < 2; r++) {
                int fid = t + r * 256;
                int nn = fid >> 5, kx = fid & 31;
                float cc, ss;
                compose_e2(&stab[(ic + 1) * 16 + nn][0], skint[kx], cc, ss);
                sEc[1-c][nn][kx] = cc;
                sEs[1-c][nn][kx] = ss;
            }
            CPA_WAIT0();
        }
        __syncthreads();
    }

    int s = blockIdx.y;
    #pragma unroll
    for (int p = 0; p < 2; p++) {
        float2 r0 = up2(akr[p][0]), r1 = up2(akr[p][1]);
        float2 i0 = up2(aki[p][0]), i1 = up2(aki[p][1]);
        float2 v0 = up2(avr[p][0]), v1 = up2(avr[p][1]);
        float2 w0 = up2(avi[p][0]), w1 = up2(avi[p][1]);
        int kkA = k0 + tk*4 + p*2;
        int kkB = kkA + 1;
        if (kkA < Kv) {
            *(float2*)&g_part[s][0][b][kkA][lane*2] = make_float2(r0.x, r1.x);
            *(float2*)&g_part[s][1][b][kkA][lane*2] = make_float2(i0.x, i1.x);
            *(float2*)&g_part[s][2][b][kkA][lane*2] = make_float2(v0.x, v1.x);
            *(float2*)&g_part[s][3][b][kkA][lane*2] = make_float2(w0.x, w1.x);
        }
        if (kkB < Kv) {
            *(float2*)&g_part[s][0][b][kkB][lane*2] = make_float2(r0.y, r1.y);
            *(float2*)&g_part[s][1][b][kkB][lane*2] = make_float2(i0.y, i1.y);
            *(float2*)&g_part[s][2][b][kkB][lane*2] = make_float2(v0.y, v1.y);
            *(float2*)&g_part[s][3][b][kkB][lane*2] = make_float2(w0.y, w1.y);
        }
    }
}

// ---------------- K2b: deterministic split reduction -----------------------
__global__ void k_reduce(int B)
{
    int idx = blockIdx.x * 256 + threadIdx.x;
    int total = 4 * B * KPAD * 64;
    if (idx >= total) return;
    int d  = idx & 63;
    int k  = (idx >> 6) % KPAD;
    int rb = (idx >> 6) / KPAD;
    int b  = rb % B;
    int m  = rb / B;
    if (k >= g_Kv[b]) return;
    float s = 0.f;
    #pragma unroll
    for (int sp = 0; sp < NSPLIT; sp++) s += g_part[sp][m][b][k][d];
    if (m < 2) g_kpotT[m][b][d][k] = s;
    else       g_vpot[m - 2][b][k][d] = s;
}

// ---------------- K3: logits L = Re(e * (Q @ kpot^T)) — fused compose ------
__global__ void __launch_bounds__(128) k_z(int n)
{
    int b  = blockIdx.z;
    int k0 = blockIdx.x * 64;
    int n0 = blockIdx.y * 64;
    int t  = threadIdx.x;
    int tk = t & 15;                // 16 groups x 4k
    int tn = t >> 4;                // 8 groups x 8n

    __shared__ float  sQT[64][64];   // [d][node]
    __shared__ float  sKR[64][64];   // [d][k]
    __shared__ float  sKI[64][64];   // [d][k]
    __shared__ float2 stab[64][18];
    __shared__ int4   skint[64];

    #pragma unroll
    for (int r = 0; r < 8; r++) {
        int fid = t + r * 128;
        int d = fid >> 4, nq = fid & 15;
        *(float4*)&sQT[d][nq*4] = *(const float4*)&g_QT[b][d][n0 + nq*4];
    }
    #pragma unroll
    for (int r = 0; r < 8; r++) {
        int fid = t + r * 128;
        int d = fid >> 4, kq = fid & 15;
        *(float4*)&sKR[d][kq*4] = *(const float4*)&g_kpotT[0][b][d][k0 + kq*4];
        *(float4*)&sKI[d][kq*4] = *(const float4*)&g_kpotT[1][b][d][k0 + kq*4];
    }
    {
        const float2* src = &g_tab[b][n0][0];
        float2* dst = &stab[0][0];
        for (int i = t; i < 64 * 18; i += 128) dst[i] = src[i];
    }
    if (t < 64) skint[t] = g_kint[b][k0 + t];

    unsigned long long zr2[4][4] = {}, zi2[4][4] = {};  // [n-pair][k j]
    __syncthreads();

    #pragma unroll 4
    for (int dd = 0; dd < 64; dd++) {
        float4 a0 = *(const float4*)&sQT[dd][tn*8];
        float4 a1 = *(const float4*)&sQT[dd][tn*8 + 4];
        float4 br = *(const float4*)&sKR[dd][tk*4];
        float4 bi = *(const float4*)&sKI[dd][tk*4];
        unsigned long long ap[4] = { pk2(a0.x, a0.y), pk2(a0.z, a0.w),
                                     pk2(a1.x, a1.y), pk2(a1.z, a1.w) };
        float brr[4] = {br.x, br.y, br.z, br.w};
        float bii[4] = {bi.x, bi.y, bi.z, bi.w};
        #pragma unroll
        for (int j = 0; j < 4; j++) {
            unsigned long long bb = pk2(brr[j], brr[j]);
            unsigned long long cc = pk2(bii[j], bii[j]);
            #pragma unroll
            for (int p = 0; p < 4; p++) {
                fma2(zr2[p][j], ap[p], bb);
                fma2(zi2[p][j], ap[p], cc);
            }
        }
    }

    int kbase = tk * 4;
    #pragma unroll
    for (int p = 0; p < 4; p++) {
        int nA = tn*8 + p*2;
        int nB = nA + 1;
        float4 LA, LB;
        #pragma unroll
        for (int j = 0; j < 4; j++) {
            float2 zr = up2(zr2[p][j]);
            float2 zi = up2(zi2[p][j]);
            float ec, es;
            compose_e2(&stab[nA][0], skint[kbase + j], ec, es);
            (&LA.x)[j] = ec * zr.x - es * zi.x;
            compose_e2(&stab[nB][0], skint[kbase + j], ec, es);
            (&LB.x)[j] = ec * zr.y - es * zi.y;
        }
        *(float4*)&g_L[b][n0 + nA][k0 + kbase] = LA;
        *(float4*)&g_L[b][n0 + nB][k0 + kbase] = LB;
    }
}

// ---------------- K4: per-node softmax STATS only (max, 1/sum) -------------
__global__ void __launch_bounds__(256) k_soft(int n)
{
    int b    = blockIdx.y;
    int warp = threadIdx.x >> 5;
    int lane = threadIdx.x & 31;
    int node = blockIdx.x * 8 + warp;
    if (node >= n) return;
    int Kv = g_Kv[b];

    float lg[KITER];
    float mx = -1e30f;
    #pragma unroll
    for (int i = 0; i < KITER; i++) {
        int k = lane + i * 32;
        if (k < Kv) {
            lg[i] = g_L[b][node][k];
            mx = fmaxf(mx, lg[i]);
        } else {
            lg[i] = -1e30f;
        }
    }
    #pragma unroll
    for (int o = 16; o > 0; o >>= 1) mx = fmaxf(mx, __shfl_xor_sync(0xffffffffu, mx, o));
    float sum = 0.f;
    #pragma unroll
    for (int i = 0; i < KITER; i++) {
        int k = lane + i * 32;
        if (k < Kv) sum += __expf(lg[i] - mx);
    }
    #pragma unroll
    for (int o = 16; o > 0; o >>= 1) sum += __shfl_xor_sync(0xffffffffu, sum, o);
    if (lane == 0) g_stat[b][node] = make_float2(mx, 1.0f / sum);
}

// ---------------- K5: OUT — pipelined GEMM, p = exp(L-mx)*inv inline --------
// 256 threads, 64n x 64d tile, thread tile 4n x 4d (8 packed accs).
__global__ void __launch_bounds__(256) k_out(float* __restrict__ out, int n)
{
    int b  = blockIdx.y;
    int n0 = blockIdx.x * 64;
    int Kv = g_Kv[b];
    int t  = threadIdx.x;
    int td = t & 15;                // 16 groups x 4d
    int tn = t >> 4;                // 16 groups x 4n

    __shared__ float2 stab[64][18];
    __shared__ float  sWr[2][16][68], sWi[2][16][68];  // [buf][kk][node] (+pad)
    __shared__ float  sVr[2][16][64], sVi[2][16][64];  // [buf][kk][d] (sVi negated)
    __shared__ int4   skint[KPAD];
    __shared__ float  sMx[64], sInv[64];

    {
        const float2* src = &g_tab[b][n0][0];
        float2* dst = &stab[0][0];
        for (int i = t; i < 64 * 18; i += 256) dst[i] = src[i];
    }
    for (int i = t; i < KPAD; i += 256) skint[i] = g_kint[b][i];
    if (t < 64) {
        float2 st = g_stat[b][n0 + t];
        sMx[t]  = st.x;
        sInv[t] = st.y;
    }

    unsigned long long acc2[2][4] = {};   // [n-pair][d j]

    float  pL[4];
    float4 pvr, pvi;
    // prefetch chunk 0 (L values + vpot) — gmem only, no smem dependency
    #pragma unroll
    for (int r = 0; r < 4; r++) {
        int fid = t + r * 256;
        pL[r] = g_L[b][n0 + (fid >> 4)][fid & 15];
    }
    {
        int kk = t >> 4, dq = t & 15;
        pvr = *(const float4*)&g_vpot[0][b][kk][dq*4];
        pvi = *(const float4*)&g_vpot[1][b][kk][dq*4];
    }
    __syncthreads();                      // stab/skint/sMx/sInv ready
    // stage chunk 0
    #pragma unroll
    for (int r = 0; r < 4; r++) {
        int fid = t + r * 256;
        int kk = fid & 15, node = fid >> 4;
        float p = (kk < Kv) ? __expf(pL[r] - sMx[node]) * sInv[node] : 0.f;
        float c, s;
        compose_e2(&stab[node][0], skint[kk], c, s);
        sWr[0][kk][node] = p * c;
        sWi[0][kk][node] = p * s;
    }
    {
        int kk = t >> 4, dq = t & 15;
        *(float4*)&sVr[0][kk][dq*4] = pvr;
        *(float4*)&sVi[0][kk][dq*4] = make_float4(-pvi.x, -pvi.y, -pvi.z, -pvi.w);
    }
    __syncthreads();

    const int nch = KPAD / 16;            // 20
    for (int ic = 0; ic < nch; ic++) {
        int c = ic & 1;
        if (ic + 1 < nch) {               // prefetch next chunk
            int k0n = (ic + 1) * 16;
            #pragma unroll
            for (int r = 0; r < 4; r++) {
                int fid = t + r * 256;
                pL[r] = g_L[b][n0 + (fid >> 4)][k0n + (fid & 15)];
            }
            int kk = t >> 4, dq = t & 15;
            pvr = *(const float4*)&g_vpot[0][b][k0n + kk][dq*4];
            pvi = *(const float4*)&g_vpot[1][b][k0n + kk][dq*4];
        }
        #pragma unroll 4
        for (int kk = 0; kk < 16; kk++) {
            float4 wr4 = *(const float4*)&sWr[c][kk][tn*4];
            float4 wi4 = *(const float4*)&sWi[c][kk][tn*4];
            float4 vr4 = *(const float4*)&sVr[c][kk][td*4];
            float4 vn4 = *(const float4*)&sVi[c][kk][td*4];
            unsigned long long wp[2] = { pk2(wr4.x, wr4.y), pk2(wr4.z, wr4.w) };
            unsigned long long ip[2] = { pk2(wi4.x, wi4.y), pk2(wi4.z, wi4.w) };
            float vr[4] = {vr4.x, vr4.y, vr4.z, vr4.w};
            float vn[4] = {vn4.x, vn4.y, vn4.z, vn4.w};
            #pragma unroll
            for (int j = 0; j < 4; j++) {
                unsigned long long bb = pk2(vr[j], vr[j]);
                unsigned long long cc = pk2(vn[j], vn[j]);
                #pragma unroll
                for (int p = 0; p < 2; p++) {
                    fma2(acc2[p][j], wp[p], bb);
                    fma2(acc2[p][j], ip[p], cc);
                }
            }
        }
        if (ic + 1 < nch) {               // stage next chunk into alt buffer
            int k0n = (ic + 1) * 16;
            #pragma unroll
            for (int r = 0; r < 4; r++) {
                int fid = t + r * 256;
                int kk = fid & 15, node = fid >> 4;
                int kg = k0n + kk;
                float p = (kg < Kv) ? __expf(pL[r] - sMx[node]) * sInv[node] : 0.f;
                float cc, ss;
                compose_e2(&stab[node][0], skint[kg], cc, ss);
                sWr[1-c][kk][node] = p * cc;
                sWi[1-c][kk][node] = p * ss;
            }
            int kk = t >> 4, dq = t & 15;
            *(float4*)&sVr[1-c][kk][dq*4] = pvr;
            *(float4*)&sVi[1-c][kk][dq*4] = make_float4(-pvi.x, -pvi.y, -pvi.z, -pvi.w);
        }
        __syncthreads();
    }

    #pragma unroll
    for (int p = 0; p < 2; p++) {
        float2 a0 = up2(acc2[p][0]), a1 = up2(acc2[p][1]), a2 = up2(acc2[p][2]), a3 = up2(acc2[p][3]);
        float* opA = out + ((size_t)(b*n + n0 + tn*4 + p*2)) * 64 + td*4;
        float* opB = opA + 64;
        *(float4*)opA = make_float4(a0.x, a1.x, a2.x, a3.x);
        *(float4*)opB = make_float4(a0.y, a1.y, a2.y, a3.y);
    }
}

// ---------------- launch -----------------------------------------------------
// k_pot stays at launch #4 (the observed ncu window). 8 launches total.
extern "C" void kernel_launch(void* const* d_in, const int* in_sizes, int n_in,
                              void* d_out, int out_size)
{
    const float* q    = (const float*)d_in[0];
    const float* kmat = (const float*)d_in[1];
    const float* vmat = (const float*)d_in[2];
    const float* pos  = (const float*)d_in[3];
    const float* cell = (const float*)d_in[4];
    // d_in[5] = batch indices (contiguous equal-size graphs; unused)

    int N = in_sizes[0] / 64;
    int B = in_sizes[4] / 9;
    int n = N / B;

    k_qT<<<dim3(n / 32, 2, B), dim3(32, 8)>>>(q, n);                 // 1
    k_build<<<B, 32>>>(cell);                                        // 2
    k_tab<<<(B * n * 18 + 255) / 256, 256>>>(pos, cell, n, B);       // 3
    k_pot<<<dim3(KPAD / 32, NSPLIT, B), 256>>>(kmat, vmat, n);       // 4 (profiled)
    int total = 4 * B * KPAD * 64;
    k_reduce<<<(total + 255) / 256, 256>>>(B);                       // 5
    k_z<<<dim3(KPAD / 64, n / 64, B), 128>>>(n);                     // 6
    k_soft<<<dim3(n / 8, B), 256>>>(n);                              // 7
    k_out<<<dim3(n / 64, B), 256>>>((float*)d_out, n);               // 8
}

// round 16
// speedup vs baseline: 1.0608x; 1.0462x over previous
#include <cuda_runtime.h>
#include <math.h>

#define KPAD   320        // >= Kv (297 for box=20, dl=4), multiple of 32
#define BMAX   8
#define NMAX   2048
#define NSPLIT 16
#define KITER  (KPAD/32)  // 10

// ---------------- scratch (zero-initialized device globals) ----------------
__device__ int    g_Kv[BMAX];
__device__ int4   g_kint[BMAX][KPAD];
__device__ float2 g_tab[BMAX][NMAX][18];       // phasor tables (cos,sin)[axis*6+m]
__device__ float  g_part[NSPLIT][4][BMAX][KPAD][64];
__device__ float  g_kpotT[2][BMAX][64][KPAD];  // k_pot re/im, [d][k] transposed
__device__ float  g_vpot[2][BMAX][KPAD][64];   // v_pot re/im, [k][d]
__device__ float  g_QT[BMAX][64][NMAX];        // Q transposed [d][n]
__device__ float  g_L[BMAX][NMAX][KPAD];       // attention logits
__device__ float  g_P[BMAX][NMAX][KPAD];       // softmax probabilities

// ---------------- packed f32x2 helpers (Blackwell FFMA2) --------------------
__device__ __forceinline__ unsigned long long pk2(float lo, float hi) {
    unsigned long long r;
    asm("mov.b64 %0, {%1, %2};" : "=l"(r) : "f"(lo), "f"(hi));
    return r;
}
__device__ __forceinline__ void fma2(unsigned long long& d,
                                     unsigned long long a, unsigned long long b) {
    asm("fma.rn.f32x2 %0, %1, %2, %0;" : "+l"(d) : "l"(a), "l"(b));
}
__device__ __forceinline__ float2 up2(unsigned long long v) {
    float2 f;
    asm("mov.b64 {%0, %1}, %2;" : "=f"(f.x), "=f"(f.y) : "l"(v));
    return f;
}

// ---------------- cp.async helpers ------------------------------------------
__device__ __forceinline__ void cpa16(void* smem, const void* gmem) {
    unsigned int sa = (unsigned int)__cvta_generic_to_shared(smem);
    asm volatile("cp.async.ca.shared.global [%0], [%1], 16;" :: "r"(sa), "l"(gmem));
}
#define CPA_COMMIT() asm volatile("cp.async.commit_group;" ::: "memory")
#define CPA_WAIT0()  asm volatile("cp.async.wait_group 0;" ::: "memory")

// ---------------- K0: valid k-list, warp-parallel ordered compaction -------
// Bit-exact emulation of reference validity (no FFMA contraction; the 21
// boundary points with |k|^2 == 25 must be INCLUDED).
__global__ void k_build(const float* __restrict__ cell)
{
    int b = blockIdx.x;
    int lane = threadIdx.x;
    float bx = cell[b*9 + 0];
    float by = cell[b*9 + 4];
    float bz = cell[b*9 + 8];
    int nkx = max(1, (int)(bx / 4.0f));
    int nky = max(1, (int)(by / 4.0f));
    int nkz = max(1, (int)(bz / 4.0f));
    const float TWOPI_SQ = 39.47841760435743f;   // (2*pi)^2
    const float KSQMAX   = 2.4674011002723395f;  // (2*pi/4)^2
    int ny = 2*nky + 1, nz = 2*nkz + 1;
    int total = (nkx + 1) * ny * nz;
    int cnt = 0;
    for (int base = 0; base < total; base += 32) {
        int idx = base + lane;
        bool valid = false;
        int kx = 0, ky = 0, kz = 0;
        if (idx < total) {
            kx = idx / (ny * nz);
            int r = idx % (ny * nz);
            ky = r / nz - nky;
            kz = r % nz - nkz;
            float fx = __fdiv_rn((float)kx, bx);
            float fy = __fdiv_rn((float)ky, by);
            float fz = __fdiv_rn((float)kz, bz);
            float sx = __fmul_rn(fx, fx);
            float sy = __fmul_rn(fy, fy);
            float sz = __fmul_rn(fz, fz);
            float s  = __fadd_rn(__fadd_rn(sx, sy), sz);
            float ksq = __fmul_rn(TWOPI_SQ, s);
            valid = (ksq <= KSQMAX) && (ksq > 0.0f);
        }
        unsigned m = __ballot_sync(0xffffffffu, valid);
        int pos = cnt + __popc(m & ((1u << lane) - 1u));
        if (valid && pos < KPAD) g_kint[b][pos] = make_int4(kx, ky, kz, 0);
        cnt += __popc(m);
    }
    if (lane == 0) g_Kv[b] = min(cnt, KPAD);
}

// ---------------- K0b: transpose Q into [d][n] -------------------------------
__global__ void k_qT(const float* __restrict__ qmat, int n)
{
    __shared__ float tile[32][33];
    int b  = blockIdx.z;
    int n0 = blockIdx.x * 32;
    int d0 = blockIdx.y * 32;
    int x = threadIdx.x, y = threadIdx.y;
    #pragma unroll
    for (int i = 0; i < 32; i += 8)
        tile[y + i][x] = qmat[((size_t)(b*n + n0 + y + i)) * 64 + d0 + x];
    __syncthreads();
    #pragma unroll
    for (int i = 0; i < 32; i += 8)
        g_QT[b][d0 + y + i][n0 + x] = tile[x][y + i];
}

// ---------------- K0c: phasor tables, computed ONCE per (b, node) ----------
__global__ void k_tab(const float* __restrict__ pos,
                      const float* __restrict__ cell, int n, int B)
{
    int idx = blockIdx.x * 256 + threadIdx.x;
    int total = B * n * 18;
    if (idx >= total) return;
    int e    = idx % 18;
    int node = (idx / 18) % n;
    int b    = idx / (18 * n);
    int a = e / 6, m = e % 6;
    float box = cell[b*9 + a*4];
    float u = pos[((size_t)(b*n + node)) * 3 + a] / box;
    float t = u * (float)m;
    t -= floorf(t);
    float sv, cv;
    sincospif(2.0f * t, &sv, &cv);
    g_tab[b][node][e] = make_float2(cv, sv);
}

// compose e^{i 2pi k.u} from a node's phasor table (float2 (cos,sin)[a*6+m])
__device__ __forceinline__ void compose_e2(const float2* tab, int4 kv,
                                           float& c, float& s)
{
    float2 ex = tab[kv.x];
    float2 ey = tab[6 + abs(kv.y)];
    float sy = (kv.y < 0) ? -ey.y : ey.y;
    float2 ez = tab[12 + abs(kv.z)];
    float sz = (kv.z < 0) ? -ez.y : ez.y;
    float c1 = ex.x*ey.x - ex.y*sy;
    float s1 = ex.x*sy + ex.y*ey.x;
    c = c1*ez.x - s1*sz;
    s = c1*sz + s1*ez.x;
}

// ---------------- K2: k_pot/v_pot partials — 32k x 64d CTA tile -------------
// (R14 variant: launch_bounds(256,4), regs 63, occ 43.7%, 64.1us verified)
__global__ void __launch_bounds__(256, 4) k_pot(const float* __restrict__ kmat,
                                                const float* __restrict__ vmat,
                                                int n)
{
    int b  = blockIdx.z;
    int Kv = g_Kv[b];
    int k0 = blockIdx.x * 32;
    int nper = n / NSPLIT;          // 128
    int n0 = blockIdx.y * nper;
    int t  = threadIdx.x;
    int tk   = t >> 5;              // warp id 0..7 -> k base tk*4
    int lane = t & 31;              // d pair: d = lane*2

    __shared__ float2 stab[128][18];                 // 18 KB (nper nodes)
    __shared__ float  sEc[2][16][32], sEs[2][16][32];// 8 KB
    __shared__ float  sK[2][16][64],  sV[2][16][64]; // 16 KB
    __shared__ int4   skint[32];

    {
        const float2* src = &g_tab[b][n0][0];
        float2* dst = &stab[0][0];
        for (int i = t; i < 128 * 18; i += 256) dst[i] = src[i];
    }
    if (t < 32) skint[t] = g_kint[b][k0 + t];

    int lnode = t >> 4, ldq = t & 15;   // tile loader mapping (16 nodes x 16 f4)
    const float4* kp = (const float4*)kmat + (size_t)(b*n + n0 + lnode) * 16 + ldq;
    const float4* vp = (const float4*)vmat + (size_t)(b*n + n0 + lnode) * 16 + ldq;

    unsigned long long akr[2][2] = {}, aki[2][2] = {}, avr[2][2] = {}, avi[2][2] = {};

    cpa16(&sK[0][lnode][ldq*4], kp);
    cpa16(&sV[0][lnode][ldq*4], vp);
    CPA_COMMIT();
    __syncthreads();
    #pragma unroll
    for (int r = 0; r < 2; r++) {
        int fid = t + r * 256;
        int nn = fid >> 5, kx = fid & 31;
        float c, s;
        compose_e2(&stab[nn][0], skint[kx], c, s);
        sEc[0][nn][kx] = c;
        sEs[0][nn][kx] = s;
    }
    CPA_WAIT0();
    __syncthreads();

    const int nchunks = nper / 16;         // 8
    for (int ic = 0; ic < nchunks; ic++) {
        int c = ic & 1;
        if (ic + 1 < nchunks) {
            cpa16(&sK[1-c][lnode][ldq*4], kp + (ic + 1) * 256);
            cpa16(&sV[1-c][lnode][ldq*4], vp + (ic + 1) * 256);
            CPA_COMMIT();
        }
        #pragma unroll
        for (int nn = 0; nn < 16; nn++) {
            float4 ec4 = *(const float4*)&sEc[c][nn][tk*4];   // warp-uniform (bcast)
            float4 es4 = *(const float4*)&sEs[c][nn][tk*4];
            float2 xk2 = *(const float2*)&sK[c][nn][lane*2];
            float2 xv2 = *(const float2*)&sV[c][nn][lane*2];
            unsigned long long ecp0 = pk2(ec4.x, ec4.y), ecp1 = pk2(ec4.z, ec4.w);
            unsigned long long esp0 = pk2(es4.x, es4.y), esp1 = pk2(es4.z, es4.w);
            unsigned long long bk0 = pk2(xk2.x, xk2.x), bk1 = pk2(xk2.y, xk2.y);
            unsigned long long bv0 = pk2(xv2.x, xv2.x), bv1 = pk2(xv2.y, xv2.y);
            fma2(akr[0][0], ecp0, bk0); fma2(akr[0][1], ecp0, bk1);
            fma2(akr[1][0], ecp1, bk0); fma2(akr[1][1], ecp1, bk1);
            fma2(aki[0][0], esp0, bk0); fma2(aki[0][1], esp0, bk1);
            fma2(aki[1][0], esp1, bk0); fma2(aki[1][1], esp1, bk1);
            fma2(avr[0][0], ecp0, bv0); fma2(avr[0][1], ecp0, bv1);
            fma2(avr[1][0], ecp1, bv0); fma2(avr[1][1], ecp1, bv1);
            fma2(avi[0][0], esp0, bv0); fma2(avi[0][1], esp0, bv1);
            fma2(avi[1][0], esp1, bv0); fma2(avi[1][1], esp1, bv1);
        }
        if (ic + 1 < nchunks) {
            #pragma unroll
            for (int r = 0; r < 2; r++) {
                int fid = t + r * 256;
                int nn = fid >> 5, kx = fid & 31;
                float cc, ss;
                compose_e2(&stab[(ic + 1) * 16 + nn][0], skint[kx], cc, ss);
                sEc[1-c][nn][kx] = cc;
                sEs[1-c][nn][kx] = ss;
            }
            CPA_WAIT0();
        }
        __syncthreads();
    }

    int s = blockIdx.y;
    #pragma unroll
    for (int p = 0; p < 2; p++) {
        float2 r0 = up2(akr[p][0]), r1 = up2(akr[p][1]);
        float2 i0 = up2(aki[p][0]), i1 = up2(aki[p][1]);
        float2 v0 = up2(avr[p][0]), v1 = up2(avr[p][1]);
        float2 w0 = up2(avi[p][0]), w1 = up2(avi[p][1]);
        int kkA = k0 + tk*4 + p*2;
        int kkB = kkA + 1;
        if (kkA < Kv) {
            *(float2*)&g_part[s][0][b][kkA][lane*2] = make_float2(r0.x, r1.x);
            *(float2*)&g_part[s][1][b][kkA][lane*2] = make_float2(i0.x, i1.x);
            *(float2*)&g_part[s][2][b][kkA][lane*2] = make_float2(v0.x, v1.x);
            *(float2*)&g_part[s][3][b][kkA][lane*2] = make_float2(w0.x, w1.x);
        }
        if (kkB < Kv) {
            *(float2*)&g_part[s][0][b][kkB][lane*2] = make_float2(r0.y, r1.y);
            *(float2*)&g_part[s][1][b][kkB][lane*2] = make_float2(i0.y, i1.y);
            *(float2*)&g_part[s][2][b][kkB][lane*2] = make_float2(v0.y, v1.y);
            *(float2*)&g_part[s][3][b][kkB][lane*2] = make_float2(w0.y, w1.y);
        }
    }
}

// ---------------- K2b: deterministic split reduction -----------------------
__global__ void k_reduce(int B)
{
    int idx = blockIdx.x * 256 + threadIdx.x;
    int total = 4 * B * KPAD * 64;
    if (idx >= total) return;
    int d  = idx & 63;
    int k  = (idx >> 6) % KPAD;
    int rb = (idx >> 6) / KPAD;
    int b  = rb % B;
    int m  = rb / B;
    if (k >= g_Kv[b]) return;
    float s = 0.f;
    #pragma unroll
    for (int sp = 0; sp < NSPLIT; sp++) s += g_part[sp][m][b][k][d];
    if (m < 2) g_kpotT[m][b][d][k] = s;
    else       g_vpot[m - 2][b][k][d] = s;
}

// ---------------- K3: logits L = Re(e * (Q @ kpot^T)) — fused compose ------
__global__ void __launch_bounds__(128) k_z(int n)
{
    int b  = blockIdx.z;
    int k0 = blockIdx.x * 64;
    int n0 = blockIdx.y * 64;
    int t  = threadIdx.x;
    int tk = t & 15;                // 16 groups x 4k
    int tn = t >> 4;                // 8 groups x 8n

    __shared__ float  sQT[64][64];   // [d][node]
    __shared__ float  sKR[64][64];   // [d][k]
    __shared__ float  sKI[64][64];   // [d][k]
    __shared__ float2 stab[64][18];
    __shared__ int4   skint[64];

    #pragma unroll
    for (int r = 0; r < 8; r++) {
        int fid = t + r * 128;
        int d = fid >> 4, nq = fid & 15;
        *(float4*)&sQT[d][nq*4] = *(const float4*)&g_QT[b][d][n0 + nq*4];
    }
    #pragma unroll
    for (int r = 0; r < 8; r++) {
        int fid = t + r * 128;
        int d = fid >> 4, kq = fid & 15;
        *(float4*)&sKR[d][kq*4] = *(const float4*)&g_kpotT[0][b][d][k0 + kq*4];
        *(float4*)&sKI[d][kq*4] = *(const float4*)&g_kpotT[1][b][d][k0 + kq*4];
    }
    {
        const float2* src = &g_tab[b][n0][0];
        float2* dst = &stab[0][0];
        for (int i = t; i < 64 * 18; i += 128) dst[i] = src[i];
    }
    if (t < 64) skint[t] = g_kint[b][k0 + t];

    unsigned long long zr2[4][4] = {}, zi2[4][4] = {};  // [n-pair][k j]
    __syncthreads();

    #pragma unroll 4
    for (int dd = 0; dd < 64; dd++) {
        float4 a0 = *(const float4*)&sQT[dd][tn*8];
        float4 a1 = *(const float4*)&sQT[dd][tn*8 + 4];
        float4 br = *(const float4*)&sKR[dd][tk*4];
        float4 bi = *(const float4*)&sKI[dd][tk*4];
        unsigned long long ap[4] = { pk2(a0.x, a0.y), pk2(a0.z, a0.w),
                                     pk2(a1.x, a1.y), pk2(a1.z, a1.w) };
        float brr[4] = {br.x, br.y, br.z, br.w};
        float bii[4] = {bi.x, bi.y, bi.z, bi.w};
        #pragma unroll
        for (int j = 0; j < 4; j++) {
            unsigned long long bb = pk2(brr[j], brr[j]);
            unsigned long long cc = pk2(bii[j], bii[j]);
            #pragma unroll
            for (int p = 0; p < 4; p++) {
                fma2(zr2[p][j], ap[p], bb);
                fma2(zi2[p][j], ap[p], cc);
            }
        }
    }

    int kbase = tk * 4;
    #pragma unroll
    for (int p = 0; p < 4; p++) {
        int nA = tn*8 + p*2;
        int nB = nA + 1;
        float4 LA, LB;
        #pragma unroll
        for (int j = 0; j < 4; j++) {
            float2 zr = up2(zr2[p][j]);
            float2 zi = up2(zi2[p][j]);
            float ec, es;
            compose_e2(&stab[nA][0], skint[kbase + j], ec, es);
            (&LA.x)[j] = ec * zr.x - es * zi.x;
            compose_e2(&stab[nB][0], skint[kbase + j], ec, es);
            (&LB.x)[j] = ec * zr.y - es * zi.y;
        }
        *(float4*)&g_L[b][n0 + nA][k0 + kbase] = LA;
        *(float4*)&g_L[b][n0 + nB][k0 + kbase] = LB;
    }
}

// ---------------- K4: per-node softmax (pure streaming); writes P ----------
__global__ void __launch_bounds__(256) k_soft(int n)
{
    int b    = blockIdx.y;
    int warp = threadIdx.x >> 5;
    int lane = threadIdx.x & 31;
    int node = blockIdx.x * 8 + warp;
    if (node >= n) return;
    int Kv = g_Kv[b];

    float lg[KITER];
    float mx = -1e30f;
    #pragma unroll
    for (int i = 0; i < KITER; i++) {
        int k = lane + i * 32;
        if (k < Kv) {
            lg[i] = g_L[b][node][k];
            mx = fmaxf(mx, lg[i]);
        } else {
            lg[i] = -1e30f;
        }
    }
    #pragma unroll
    for (int o = 16; o > 0; o >>= 1) mx = fmaxf(mx, __shfl_xor_sync(0xffffffffu, mx, o));
    float sum = 0.f;
    #pragma unroll
    for (int i = 0; i < KITER; i++) {
        int k = lane + i * 32;
        if (k < Kv) {
            float p = __expf(lg[i] - mx);
            lg[i] = p;
            sum += p;
        }
    }
    #pragma unroll
    for (int o = 16; o > 0; o >>= 1) sum += __shfl_xor_sync(0xffffffffu, sum, o);
    float inv = 1.0f / sum;
    #pragma unroll
    for (int i = 0; i < KITER; i++) {
        int k = lane + i * 32;
        if (k < Kv) g_P[b][node][k] = lg[i] * inv;
    }
}

// ---------------- K5: OUT — pipelined, double-buffered (R13 verified) -------
__global__ void __launch_bounds__(128) k_out(float* __restrict__ out, int n)
{
    int b  = blockIdx.y;
    int n0 = blockIdx.x * 64;
    int t  = threadIdx.x;
    int td = t & 15;                // 16 groups x 4d
    int tn = t >> 4;                // 8 groups x 8n

    __shared__ float2 stab[64][18];
    __shared__ float  sWr[2][16][68], sWi[2][16][68];  // [buf][kk][node] (+pad)
    __shared__ float  sVr[2][16][64], sVi[2][16][64];  // [buf][kk][d] (sVi negated)
    __shared__ int4   skint[KPAD];

    {
        const float2* src = &g_tab[b][n0][0];
        float2* dst = &stab[0][0];
        for (int i = t; i < 64 * 18; i += 128) dst[i] = src[i];
    }
    for (int i = t; i < KPAD; i += 128) skint[i] = g_kint[b][i];

    unsigned long long acc2[4][4] = {};   // [n-pair][d j]

    float  pP[8];
    float4 pvr[2], pvi[2];
    // prologue: prefetch chunk 0
    #pragma unroll
    for (int r = 0; r < 8; r++) {
        int fid = t + r * 128;
        pP[r] = g_P[b][n0 + (fid >> 4)][fid & 15];
    }
    #pragma unroll
    for (int r = 0; r < 2; r++) {
        int fid = t + r * 128;
        int kk = fid >> 4, dq = fid & 15;
        pvr[r] = *(const float4*)&g_vpot[0][b][kk][dq*4];
        pvi[r] = *(const float4*)&g_vpot[1][b][kk][dq*4];
    }
    __syncthreads();                      // stab/skint ready
    #pragma unroll
    for (int r = 0; r < 8; r++) {
        int fid = t + r * 128;
        int kk = fid & 15, node = fid >> 4;
        float c, s;
        compose_e2(&stab[node][0], skint[kk], c, s);
        sWr[0][kk][node] = pP[r] * c;
        sWi[0][kk][node] = pP[r] * s;
    }
    #pragma unroll
    for (int r = 0; r < 2; r++) {
        int fid = t + r * 128;
        int kk = fid >> 4, dq = fid & 15;
        *(float4*)&sVr[0][kk][dq*4] = pvr[r];
        *(float4*)&sVi[0][kk][dq*4] = make_float4(-pvi[r].x, -pvi[r].y, -pvi[r].z, -pvi[r].w);
    }
    __syncthreads();

    const int nch = KPAD / 16;            // 20
    for (int ic = 0; ic < nch; ic++) {
        int c = ic & 1;
        if (ic + 1 < nch) {               // prefetch next chunk
            int k0n = (ic + 1) * 16;
            #pragma unroll
            for (int r = 0; r < 8; r++) {
                int fid = t + r * 128;
                pP[r] = g_P[b][n0 + (fid >> 4)][k0n + (fid & 15)];
            }
            #pragma unroll
            for (int r = 0; r < 2; r++) {
                int fid = t + r * 128;
                int kk = fid >> 4, dq = fid & 15;
                pvr[r] = *(const float4*)&g_vpot[0][b][k0n + kk][dq*4];
                pvi[r] = *(const float4*)&g_vpot[1][b][k0n + kk][dq*4];
            }
        }
        #pragma unroll 4
        for (int kk = 0; kk < 16; kk++) {
            float4 wra = *(const float4*)&sWr[c][kk][tn*8];
            float4 wrb = *(const float4*)&sWr[c][kk][tn*8 + 4];
            float4 wia = *(const float4*)&sWi[c][kk][tn*8];
            float4 wib = *(const float4*)&sWi[c][kk][tn*8 + 4];
            float4 vr4 = *(const float4*)&sVr[c][kk][td*4];
            float4 vn4 = *(const float4*)&sVi[c][kk][td*4];
            unsigned long long wp[4] = { pk2(wra.x, wra.y), pk2(wra.z, wra.w),
                                         pk2(wrb.x, wrb.y), pk2(wrb.z, wrb.w) };
            unsigned long long ip[4] = { pk2(wia.x, wia.y), pk2(wia.z, wia.w),
                                         pk2(wib.x, wib.y), pk2(wib.z, wib.w) };
            float vr[4] = {vr4.x, vr4.y, vr4.z, vr4.w};
            float vn[4] = {vn4.x, vn4.y, vn4.z, vn4.w};
            #pragma unroll
            for (int j = 0; j < 4; j++) {
                unsigned long long bb = pk2(vr[j], vr[j]);
                unsigned long long cc = pk2(vn[j], vn[j]);
                #pragma unroll
                for (int p = 0; p < 4; p++) {
                    fma2(acc2[p][j], wp[p], bb);
                    fma2(acc2[p][j], ip[p], cc);
                }
            }
        }
        if (ic + 1 < nch) {               // stage next chunk into alt buffer
            int k0n = (ic + 1) * 16;
            #pragma unroll
            for (int r = 0; r < 8; r++) {
                int fid = t + r * 128;
                int kk = fid & 15, node = fid >> 4;
                float cc, ss;
                compose_e2(&stab[node][0], skint[k0n + kk], cc, ss);
                sWr[1-c][kk][node] = pP[r] * cc;
                sWi[1-c][kk][node] = pP[r] * ss;
            }
            #pragma unroll
            for (int r = 0; r < 2; r++) {
                int fid = t + r * 128;
                int kk = fid >> 4, dq = fid & 15;
                *(float4*)&sVr[1-c][kk][dq*4] = pvr[r];
                *(float4*)&sVi[1-c][kk][dq*4] = make_float4(-pvi[r].x, -pvi[r].y, -pvi[r].z, -pvi[r].w);
            }
        }
        __syncthreads();
    }

    #pragma unroll
    for (int p = 0; p < 4; p++) {
        float2 a0 = up2(acc2[p][0]), a1 = up2(acc2[p][1]), a2 = up2(acc2[p][2]), a3 = up2(acc2[p][3]);
        float* opA = out + ((size_t)(b*n + n0 + tn*8 + p*2)) * 64 + td*4;
        float* opB = opA + 64;
        *(float4*)opA = make_float4(a0.x, a1.x, a2.x, a3.x);
        *(float4*)opB = make_float4(a0.y, a1.y, a2.y, a3.y);
    }
}

// ---------------- launch -----------------------------------------------------
// k_pot stays at launch #4 (the observed ncu window). 8 launches total.
extern "C" void kernel_launch(void* const* d_in, const int* in_sizes, int n_in,
                              void* d_out, int out_size)
{
    const float* q    = (const float*)d_in[0];
    const float* kmat = (const float*)d_in[1];
    const float* vmat = (const float*)d_in[2];
    const float* pos  = (const float*)d_in[3];
    const float* cell = (const float*)d_in[4];
    // d_in[5] = batch indices (contiguous equal-size graphs; unused)

    int N = in_sizes[0] / 64;
    int B = in_sizes[4] / 9;
    int n = N / B;

    k_qT<<<dim3(n / 32, 2, B), dim3(32, 8)>>>(q, n);                 // 1
    k_build<<<B, 32>>>(cell);                                        // 2
    k_tab<<<(B * n * 18 + 255) / 256, 256>>>(pos, cell, n, B);       // 3
    k_pot<<<dim3(KPAD / 32, NSPLIT, B), 256>>>(kmat, vmat, n);       // 4 (profiled)
    int total = 4 * B * KPAD * 64;
    k_reduce<<<(total + 255) / 256, 256>>>(B);                       // 5
    k_z<<<dim3(KPAD / 64, n / 64, B), 128>>>(n);                     // 6
    k_soft<<<dim3(n / 8, B), 256>>>(n);                              // 7
    k_out<<<dim3(n / 64, B), 128>>>((float*)d_out, n);               // 8
}

// round 17
// speedup vs baseline: 1.0739x; 1.0123x over previous
#include <cuda_runtime.h>
#include <math.h>

#define KPAD   320        // >= Kv (257 canonical for box=20, dl=4), mult of 64
#define BMAX   8
#define NMAX   2048
#define NSPLIT 16
#define KITER  (KPAD/32)  // 10

// ---------------- scratch (zero-initialized device globals) ----------------
__device__ int    g_Kv[BMAX];
__device__ int4   g_kint[BMAX][KPAD];
__device__ float  g_kw[BMAX][KPAD];            // k weight: 2 for kx=0 conj pairs
__device__ float2 g_tab[BMAX][NMAX][18];       // phasor tables (cos,sin)[axis*6+m]
__device__ float  g_part[NSPLIT][4][BMAX][KPAD][64];
__device__ float  g_kpotT[2][BMAX][64][KPAD];  // k_pot re/im, [d][k] transposed
__device__ float  g_vpot[2][BMAX][KPAD][64];   // v_pot re/im, [k][d]
__device__ float  g_QT[BMAX][64][NMAX];        // Q transposed [d][n]
__device__ float  g_L[BMAX][NMAX][KPAD];       // attention logits
__device__ float  g_P[BMAX][NMAX][KPAD];       // weighted softmax probabilities

// ---------------- packed f32x2 helpers (Blackwell FFMA2) --------------------
__device__ __forceinline__ unsigned long long pk2(float lo, float hi) {
    unsigned long long r;
    asm("mov.b64 %0, {%1, %2};" : "=l"(r) : "f"(lo), "f"(hi));
    return r;
}
__device__ __forceinline__ void fma2(unsigned long long& d,
                                     unsigned long long a, unsigned long long b) {
    asm("fma.rn.f32x2 %0, %1, %2, %0;" : "+l"(d) : "l"(a), "l"(b));
}
__device__ __forceinline__ float2 up2(unsigned long long v) {
    float2 f;
    asm("mov.b64 {%0, %1}, %2;" : "=f"(f.x), "=f"(f.y) : "l"(v));
    return f;
}

// ---------------- cp.async helpers ------------------------------------------
__device__ __forceinline__ void cpa16(void* smem, const void* gmem) {
    unsigned int sa = (unsigned int)__cvta_generic_to_shared(smem);
    asm volatile("cp.async.ca.shared.global [%0], [%1], 16;" :: "r"(sa), "l"(gmem));
}
#define CPA_COMMIT() asm volatile("cp.async.commit_group;" ::: "memory")
#define CPA_WAIT0()  asm volatile("cp.async.wait_group 0;" ::: "memory")

// ---------------- K0: valid k-list with conjugate-pair folding --------------
// Bit-exact emulation of reference validity (no FFMA contraction; the 21
// boundary points with |k|^2 == 25 must be INCLUDED). In the kx=0 plane,
// (0,ky,kz) and (0,-ky,-kz) are exact conjugates with EQUAL logits, so keep
// only the canonical member (ky>0, or ky==0 && kz>0) with weight 2; all
// kx>0 points have no partner in the half-space list -> weight 1.
__global__ void k_build(const float* __restrict__ cell)
{
    int b = blockIdx.x;
    int lane = threadIdx.x;
    float bx = cell[b*9 + 0];
    float by = cell[b*9 + 4];
    float bz = cell[b*9 + 8];
    int nkx = max(1, (int)(bx / 4.0f));
    int nky = max(1, (int)(by / 4.0f));
    int nkz = max(1, (int)(bz / 4.0f));
    const float TWOPI_SQ = 39.47841760435743f;   // (2*pi)^2
    const float KSQMAX   = 2.4674011002723395f;  // (2*pi/4)^2
    int ny = 2*nky + 1, nz = 2*nkz + 1;
    int total = (nkx + 1) * ny * nz;
    int cnt = 0;
    for (int base = 0; base < total; base += 32) {
        int idx = base + lane;
        bool keep = false;
        int kx = 0, ky = 0, kz = 0;
        if (idx < total) {
            kx = idx / (ny * nz);
            int r = idx % (ny * nz);
            ky = r / nz - nky;
            kz = r % nz - nkz;
            float fx = __fdiv_rn((float)kx, bx);
            float fy = __fdiv_rn((float)ky, by);
            float fz = __fdiv_rn((float)kz, bz);
            float sx = __fmul_rn(fx, fx);
            float sy = __fmul_rn(fy, fy);
            float sz = __fmul_rn(fz, fz);
            float s  = __fadd_rn(__fadd_rn(sx, sy), sz);
            float ksq = __fmul_rn(TWOPI_SQ, s);
            bool valid = (ksq <= KSQMAX) && (ksq > 0.0f);
            bool canon = (kx > 0) || (ky > 0) || (ky == 0 && kz > 0);
            keep = valid && canon;
        }
        unsigned m = __ballot_sync(0xffffffffu, keep);
        int pos = cnt + __popc(m & ((1u << lane) - 1u));
        if (keep && pos < KPAD) {
            g_kint[b][pos] = make_int4(kx, ky, kz, 0);
            g_kw[b][pos]   = (kx == 0) ? 2.0f : 1.0f;
        }
        cnt += __popc(m);
    }
    if (lane == 0) g_Kv[b] = min(cnt, KPAD);
}

// ---------------- K0b: transpose Q into [d][n] -------------------------------
__global__ void k_qT(const float* __restrict__ qmat, int n)
{
    __shared__ float tile[32][33];
    int b  = blockIdx.z;
    int n0 = blockIdx.x * 32;
    int d0 = blockIdx.y * 32;
    int x = threadIdx.x, y = threadIdx.y;
    #pragma unroll
    for (int i = 0; i < 32; i += 8)
        tile[y + i][x] = qmat[((size_t)(b*n + n0 + y + i)) * 64 + d0 + x];
    __syncthreads();
    #pragma unroll
    for (int i = 0; i < 32; i += 8)
        g_QT[b][d0 + y + i][n0 + x] = tile[x][y + i];
}

// ---------------- K0c: phasor tables, computed ONCE per (b, node) ----------
__global__ void k_tab(const float* __restrict__ pos,
                      const float* __restrict__ cell, int n, int B)
{
    int idx = blockIdx.x * 256 + threadIdx.x;
    int total = B * n * 18;
    if (idx >= total) return;
    int e    = idx % 18;
    int node = (idx / 18) % n;
    int b    = idx / (18 * n);
    int a = e / 6, m = e % 6;
    float box = cell[b*9 + a*4];
    float u = pos[((size_t)(b*n + node)) * 3 + a] / box;
    float t = u * (float)m;
    t -= floorf(t);
    float sv, cv;
    sincospif(2.0f * t, &sv, &cv);
    g_tab[b][node][e] = make_float2(cv, sv);
}

// compose e^{i 2pi k.u} from a node's phasor table (float2 (cos,sin)[a*6+m])
__device__ __forceinline__ void compose_e2(const float2* tab, int4 kv,
                                           float& c, float& s)
{
    float2 ex = tab[kv.x];
    float2 ey = tab[6 + abs(kv.y)];
    float sy = (kv.y < 0) ? -ey.y : ey.y;
    float2 ez = tab[12 + abs(kv.z)];
    float sz = (kv.z < 0) ? -ez.y : ez.y;
    float c1 = ex.x*ey.x - ex.y*sy;
    float s1 = ex.x*sy + ex.y*ey.x;
    c = c1*ez.x - s1*sz;
    s = c1*sz + s1*ez.x;
}

// ---------------- K2: k_pot/v_pot partials — 32k x 64d CTA tile -------------
// (R14 variant + early-out: with Kv=257, k-block 9 exits -> 9/10 blocks work)
__global__ void __launch_bounds__(256, 4) k_pot(const float* __restrict__ kmat,
                                                const float* __restrict__ vmat,
                                                int n)
{
    int b  = blockIdx.z;
    int Kv = g_Kv[b];
    int k0 = blockIdx.x * 32;
    if (k0 >= Kv) return;
    int nper = n / NSPLIT;          // 128
    int n0 = blockIdx.y * nper;
    int t  = threadIdx.x;
    int tk   = t >> 5;              // warp id 0..7 -> k base tk*4
    int lane = t & 31;              // d pair: d = lane*2

    __shared__ float2 stab[128][18];                 // 18 KB (nper nodes)
    __shared__ float  sEc[2][16][32], sEs[2][16][32];// 8 KB
    __shared__ float  sK[2][16][64],  sV[2][16][64]; // 16 KB
    __shared__ int4   skint[32];

    {
        const float2* src = &g_tab[b][n0][0];
        float2* dst = &stab[0][0];
        for (int i = t; i < 128 * 18; i += 256) dst[i] = src[i];
    }
    if (t < 32) skint[t] = g_kint[b][k0 + t];

    int lnode = t >> 4, ldq = t & 15;   // tile loader mapping (16 nodes x 16 f4)
    const float4* kp = (const float4*)kmat + (size_t)(b*n + n0 + lnode) * 16 + ldq;
    const float4* vp = (const float4*)vmat + (size_t)(b*n + n0 + lnode) * 16 + ldq;

    unsigned long long akr[2][2] = {}, aki[2][2] = {}, avr[2][2] = {}, avi[2][2] = {};

    cpa16(&sK[0][lnode][ldq*4], kp);
    cpa16(&sV[0][lnode][ldq*4], vp);
    CPA_COMMIT();
    __syncthreads();
    #pragma unroll
    for (int r = 0; r < 2; r++) {
        int fid = t + r * 256;
        int nn = fid >> 5, kx = fid & 31;
        float c, s;
        compose_e2(&stab[nn][0], skint[kx], c, s);
        sEc[0][nn][kx] = c;
        sEs[0][nn][kx] = s;
    }
    CPA_WAIT0();
    __syncthreads();

    const int nchunks = nper / 16;         // 8
    for (int ic = 0; ic < nchunks; ic++) {
        int c = ic & 1;
        if (ic + 1 < nchunks) {
            cpa16(&sK[1-c][lnode][ldq*4], kp + (ic + 1) * 256);
            cpa16(&sV[1-c][lnode][ldq*4], vp + (ic + 1) * 256);
            CPA_COMMIT();
        }
        #pragma unroll
        for (int nn = 0; nn < 16; nn++) {
            float4 ec4 = *(const float4*)&sEc[c][nn][tk*4];   // warp-uniform (bcast)
            float4 es4 = *(const float4*)&sEs[c][nn][tk*4];
            float2 xk2 = *(const float2*)&sK[c][nn][lane*2];
            float2 xv2 = *(const float2*)&sV[c][nn][lane*2];
            unsigned long long ecp0 = pk2(ec4.x, ec4.y), ecp1 = pk2(ec4.z, ec4.w);
            unsigned long long esp0 = pk2(es4.x, es4.y), esp1 = pk2(es4.z, es4.w);
            unsigned long long bk0 = pk2(xk2.x, xk2.x), bk1 = pk2(xk2.y, xk2.y);
            unsigned long long bv0 = pk2(xv2.x, xv2.x), bv1 = pk2(xv2.y, xv2.y);
            fma2(akr[0][0], ecp0, bk0); fma2(akr[0][1], ecp0, bk1);
            fma2(akr[1][0], ecp1, bk0); fma2(akr[1][1], ecp1, bk1);
            fma2(aki[0][0], esp0, bk0); fma2(aki[0][1], esp0, bk1);
            fma2(aki[1][0], esp1, bk0); fma2(aki[1][1], esp1, bk1);
            fma2(avr[0][0], ecp0, bv0); fma2(avr[0][1], ecp0, bv1);
            fma2(avr[1][0], ecp1, bv0); fma2(avr[1][1], ecp1, bv1);
            fma2(avi[0][0], esp0, bv0); fma2(avi[0][1], esp0, bv1);
            fma2(avi[1][0], esp1, bv0); fma2(avi[1][1], esp1, bv1);
        }
        if (ic + 1 < nchunks) {
            #pragma unroll
            for (int r = 0; r < 2; r++) {
                int fid = t + r * 256;
                int nn = fid >> 5, kx = fid & 31;
                float cc, ss;
                compose_e2(&stab[(ic + 1) * 16 + nn][0], skint[kx], cc, ss);
                sEc[1-c][nn][kx] = cc;
                sEs[1-c][nn][kx] = ss;
            }
            CPA_WAIT0();
        }
        __syncthreads();
    }

    int s = blockIdx.y;
    #pragma unroll
    for (int p = 0; p < 2; p++) {
        float2 r0 = up2(akr[p][0]), r1 = up2(akr[p][1]);
        float2 i0 = up2(aki[p][0]), i1 = up2(aki[p][1]);
        float2 v0 = up2(avr[p][0]), v1 = up2(avr[p][1]);
        float2 w0 = up2(avi[p][0]), w1 = up2(avi[p][1]);
        int kkA = k0 + tk*4 + p*2;
        int kkB = kkA + 1;
        if (kkA < Kv) {
            *(float2*)&g_part[s][0][b][kkA][lane*2] = make_float2(r0.x, r1.x);
            *(float2*)&g_part[s][1][b][kkA][lane*2] = make_float2(i0.x, i1.x);
            *(float2*)&g_part[s][2][b][kkA][lane*2] = make_float2(v0.x, v1.x);
            *(float2*)&g_part[s][3][b][kkA][lane*2] = make_float2(w0.x, w1.x);
        }
        if (kkB < Kv) {
            *(float2*)&g_part[s][0][b][kkB][lane*2] = make_float2(r0.y, r1.y);
            *(float2*)&g_part[s][1][b][kkB][lane*2] = make_float2(i0.y, i1.y);
            *(float2*)&g_part[s][2][b][kkB][lane*2] = make_float2(v0.y, v1.y);
            *(float2*)&g_part[s][3][b][kkB][lane*2] = make_float2(w0.y, w1.y);
        }
    }
}

// ---------------- K2b: deterministic split reduction -----------------------
__global__ void k_reduce(int B)
{
    int idx = blockIdx.x * 256 + threadIdx.x;
    int total = 4 * B * KPAD * 64;
    if (idx >= total) return;
    int d  = idx & 63;
    int k  = (idx >> 6) % KPAD;
    int rb = (idx >> 6) / KPAD;
    int b  = rb % B;
    int m  = rb / B;
    if (k >= g_Kv[b]) return;
    float s = 0.f;
    #pragma unroll
    for (int sp = 0; sp < NSPLIT; sp++) s += g_part[sp][m][b][k][d];
    if (m < 2) g_kpotT[m][b][d][k] = s;
    else       g_vpot[m - 2][b][k][d] = s;
}

// ---------------- K3: logits L = Re(e * (Q @ kpot^T)) — fused compose ------
__global__ void __launch_bounds__(128) k_z(int n)
{
    int b  = blockIdx.z;
    int k0 = blockIdx.x * 64;
    int n0 = blockIdx.y * 64;
    int t  = threadIdx.x;
    int tk = t & 15;                // 16 groups x 4k
    int tn = t >> 4;                // 8 groups x 8n

    __shared__ float  sQT[64][64];   // [d][node]
    __shared__ float  sKR[64][64];   // [d][k]
    __shared__ float  sKI[64][64];   // [d][k]
    __shared__ float2 stab[64][18];
    __shared__ int4   skint[64];

    #pragma unroll
    for (int r = 0; r < 8; r++) {
        int fid = t + r * 128;
        int d = fid >> 4, nq = fid & 15;
        *(float4*)&sQT[d][nq*4] = *(const float4*)&g_QT[b][d][n0 + nq*4];
    }
    #pragma unroll
    for (int r = 0; r < 8; r++) {
        int fid = t + r * 128;
        int d = fid >> 4, kq = fid & 15;
        *(float4*)&sKR[d][kq*4] = *(const float4*)&g_kpotT[0][b][d][k0 + kq*4];
        *(float4*)&sKI[d][kq*4] = *(const float4*)&g_kpotT[1][b][d][k0 + kq*4];
    }
    {
        const float2* src = &g_tab[b][n0][0];
        float2* dst = &stab[0][0];
        for (int i = t; i < 64 * 18; i += 128) dst[i] = src[i];
    }
    if (t < 64) skint[t] = g_kint[b][k0 + t];

    unsigned long long zr2[4][4] = {}, zi2[4][4] = {};  // [n-pair][k j]
    __syncthreads();

    #pragma unroll 4
    for (int dd = 0; dd < 64; dd++) {
        float4 a0 = *(const float4*)&sQT[dd][tn*8];
        float4 a1 = *(const float4*)&sQT[dd][tn*8 + 4];
        float4 br = *(const float4*)&sKR[dd][tk*4];
        float4 bi = *(const float4*)&sKI[dd][tk*4];
        unsigned long long ap[4] = { pk2(a0.x, a0.y), pk2(a0.z, a0.w),
                                     pk2(a1.x, a1.y), pk2(a1.z, a1.w) };
        float brr[4] = {br.x, br.y, br.z, br.w};
        float bii[4] = {bi.x, bi.y, bi.z, bi.w};
        #pragma unroll
        for (int j = 0; j < 4; j++) {
            unsigned long long bb = pk2(brr[j], brr[j]);
            unsigned long long cc = pk2(bii[j], bii[j]);
            #pragma unroll
            for (int p = 0; p < 4; p++) {
                fma2(zr2[p][j], ap[p], bb);
                fma2(zi2[p][j], ap[p], cc);
            }
        }
    }

    int kbase = tk * 4;
    #pragma unroll
    for (int p = 0; p < 4; p++) {
        int nA = tn*8 + p*2;
        int nB = nA + 1;
        float4 LA, LB;
        #pragma unroll
        for (int j = 0; j < 4; j++) {
            float2 zr = up2(zr2[p][j]);
            float2 zi = up2(zi2[p][j]);
            float ec, es;
            compose_e2(&stab[nA][0], skint[kbase + j], ec, es);
            (&LA.x)[j] = ec * zr.x - es * zi.x;
            compose_e2(&stab[nB][0], skint[kbase + j], ec, es);
            (&LB.x)[j] = ec * zr.y - es * zi.y;
        }
        *(float4*)&g_L[b][n0 + nA][k0 + kbase] = LA;
        *(float4*)&g_L[b][n0 + nB][k0 + kbase] = LB;
    }
}

// ---------------- K4: weighted softmax; writes P = w*exp/(sum w*exp) -------
__global__ void __launch_bounds__(256) k_soft(int n)
{
    int b    = blockIdx.y;
    int warp = threadIdx.x >> 5;
    int lane = threadIdx.x & 31;
    int node = blockIdx.x * 8 + warp;
    if (node >= n) return;
    int Kv = g_Kv[b];

    float lg[KITER];
    float mx = -1e30f;
    #pragma unroll
    for (int i = 0; i < KITER; i++) {
        int k = lane + i * 32;
        if (k < Kv) {
            lg[i] = g_L[b][node][k];
            mx = fmaxf(mx, lg[i]);
        } else {
            lg[i] = -1e30f;
        }
    }
    #pragma unroll
    for (int o = 16; o > 0; o >>= 1) mx = fmaxf(mx, __shfl_xor_sync(0xffffffffu, mx, o));
    float sum = 0.f;
    #pragma unroll
    for (int i = 0; i < KITER; i++) {
        int k = lane + i * 32;
        if (k < Kv) {
            float p = g_kw[b][k] * __expf(lg[i] - mx);
            lg[i] = p;
            sum += p;
        }
    }
    #pragma unroll
    for (int o = 16; o > 0; o >>= 1) sum += __shfl_xor_sync(0xffffffffu, sum, o);
    float inv = 1.0f / sum;
    #pragma unroll
    for (int i = 0; i < KITER; i++) {
        int k = lane + i * 32;
        if (k < Kv) g_P[b][node][k] = lg[i] * inv;
    }
}

// ---------------- K5: OUT — pipelined, double-buffered (R13 verified) -------
__global__ void __launch_bounds__(128) k_out(float* __restrict__ out, int n)
{
    int b  = blockIdx.y;
    int n0 = blockIdx.x * 64;
    int t  = threadIdx.x;
    int td = t & 15;                // 16 groups x 4d
    int tn = t >> 4;                // 8 groups x 8n

    __shared__ float2 stab[64][18];
    __shared__ float  sWr[2][16][68], sWi[2][16][68];  // [buf][kk][node] (+pad)
    __shared__ float  sVr[2][16][64], sVi[2][16][64];  // [buf][kk][d] (sVi negated)
    __shared__ int4   skint[KPAD];

    {
        const float2* src = &g_tab[b][n0][0];
        float2* dst = &stab[0][0];
        for (int i = t; i < 64 * 18; i += 128) dst[i] = src[i];
    }
    for (int i = t; i < KPAD; i += 128) skint[i] = g_kint[b][i];

    unsigned long long acc2[4][4] = {};   // [n-pair][d j]

    float  pP[8];
    float4 pvr[2], pvi[2];
    // prologue: prefetch chunk 0
    #pragma unroll
    for (int r = 0; r < 8; r++) {
        int fid = t + r * 128;
        pP[r] = g_P[b][n0 + (fid >> 4)][fid & 15];
    }
    #pragma unroll
    for (int r = 0; r < 2; r++) {
        int fid = t + r * 128;
        int kk = fid >> 4, dq = fid & 15;
        pvr[r] = *(const float4*)&g_vpot[0][b][kk][dq*4];
        pvi[r] = *(const float4*)&g_vpot[1][b][kk][dq*4];
    }
    __syncthreads();                      // stab/skint ready
    #pragma unroll
    for (int r = 0; r < 8; r++) {
        int fid = t + r * 128;
        int kk = fid & 15, node = fid >> 4;
        float c, s;
        compose_e2(&stab[node][0], skint[kk], c, s);
        sWr[0][kk][node] = pP[r] * c;
        sWi[0][kk][node] = pP[r] * s;
    }
    #pragma unroll
    for (int r = 0; r < 2; r++) {
        int fid = t + r * 128;
        int kk = fid >> 4, dq = fid & 15;
        *(float4*)&sVr[0][kk][dq*4] = pvr[r];
        *(float4*)&sVi[0][kk][dq*4] = make_float4(-pvi[r].x, -pvi[r].y, -pvi[r].z, -pvi[r].w);
    }
    __syncthreads();

    const int nch = KPAD / 16;            // 20
    for (int ic = 0; ic < nch; ic++) {
        int c = ic & 1;
        if (ic + 1 < nch) {               // prefetch next chunk
            int k0n = (ic + 1) * 16;
            #pragma unroll
            for (int r = 0; r < 8; r++) {
                int fid = t + r * 128;
                pP[r] = g_P[b][n0 + (fid >> 4)][k0n + (fid & 15)];
            }
            #pragma unroll
            for (int r = 0; r < 2; r++) {
                int fid = t + r * 128;
                int kk = fid >> 4, dq = fid & 15;
                pvr[r] = *(const float4*)&g_vpot[0][b][k0n + kk][dq*4];
                pvi[r] = *(const float4*)&g_vpot[1][b][k0n + kk][dq*4];
            }
        }
        #pragma unroll 4
        for (int kk = 0; kk < 16; kk++) {
            float4 wra = *(const float4*)&sWr[c][kk][tn*8];
            float4 wrb = *(const float4*)&sWr[c][kk][tn*8 + 4];
            float4 wia = *(const float4*)&sWi[c][kk][tn*8];
            float4 wib = *(const float4*)&sWi[c][kk][tn*8 + 4];
            float4 vr4 = *(const float4*)&sVr[c][kk][td*4];
            float4 vn4 = *(const float4*)&sVi[c][kk][td*4];
            unsigned long long wp[4] = { pk2(wra.x, wra.y), pk2(wra.z, wra.w),
                                         pk2(wrb.x, wrb.y), pk2(wrb.z, wrb.w) };
            unsigned long long ip[4] = { pk2(wia.x, wia.y), pk2(wia.z, wia.w),
                                         pk2(wib.x, wib.y), pk2(wib.z, wib.w) };
            float vr[4] = {vr4.x, vr4.y, vr4.z, vr4.w};
            float vn[4] = {vn4.x, vn4.y, vn4.z, vn4.w};
            #pragma unroll
            for (int j = 0; j < 4; j++) {
                unsigned long long bb = pk2(vr[j], vr[j]);
                unsigned long long cc = pk2(vn[j], vn[j]);
                #pragma unroll
                for (int p = 0; p < 4; p++) {
                    fma2(acc2[p][j], wp[p], bb);
                    fma2(acc2[p][j], ip[p], cc);
                }
            }
        }
        if (ic + 1 < nch) {               // stage next chunk into alt buffer
            int k0n = (ic + 1) * 16;
            #pragma unroll
            for (int r = 0; r < 8; r++) {
                int fid = t + r * 128;
                int kk = fid & 15, node = fid >> 4;
                float cc, ss;
                compose_e2(&stab[node][0], skint[k0n + kk], cc, ss);
                sWr[1-c][kk][node] = pP[r] * cc;
                sWi[1-c][kk][node] = pP[r] * ss;
            }
            #pragma unroll
            for (int r = 0; r < 2; r++) {
                int fid = t + r * 128;
                int kk = fid >> 4, dq = fid & 15;
                *(float4*)&sVr[1-c][kk][dq*4] = pvr[r];
                *(float4*)&sVi[1-c][kk][dq*4] = make_float4(-pvi[r].x, -pvi[r].y, -pvi[r].z, -pvi[r].w);
            }
        }
        __syncthreads();
    }

    #pragma unroll
    for (int p = 0; p < 4; p++) {
        float2 a0 = up2(acc2[p][0]), a1 = up2(acc2[p][1]), a2 = up2(acc2[p][2]), a3 = up2(acc2[p][3]);
        float* opA = out + ((size_t)(b*n + n0 + tn*8 + p*2)) * 64 + td*4;
        float* opB = opA + 64;
        *(float4*)opA = make_float4(a0.x, a1.x, a2.x, a3.x);
        *(float4*)opB = make_float4(a0.y, a1.y, a2.y, a3.y);
    }
}

// ---------------- launch -----------------------------------------------------
// k_pot stays at launch #4 (the observed ncu window). 8 launches total.
extern "C" void kernel_launch(void* const* d_in, const int* in_sizes, int n_in,
                              void* d_out, int out_size)
{
    const float* q    = (const float*)d_in[0];
    const float* kmat = (const float*)d_in[1];
    const float* vmat = (const float*)d_in[2];
    const float* pos  = (const float*)d_in[3];
    const float* cell = (const float*)d_in[4];
    // d_in[5] = batch indices (contiguous equal-size graphs; unused)

    int N = in_sizes[0] / 64;
    int B = in_sizes[4] / 9;
    int n = N / B;

    k_qT<<<dim3(n / 32, 2, B), dim3(32, 8)>>>(q, n);                 // 1
    k_build<<<B, 32>>>(cell);                                        // 2
    k_tab<<<(B * n * 18 + 255) / 256, 256>>>(pos, cell, n, B);       // 3
    k_pot<<<dim3(KPAD / 32, NSPLIT, B), 256>>>(kmat, vmat, n);       // 4 (profiled)
    int total = 4 * B * KPAD * 64;
    k_reduce<<<(total + 255) / 256, 256>>>(B);                       // 5
    k_z<<<dim3(KPAD / 64, n / 64, B), 128>>>(n);                     // 6
    k_soft<<<dim3(n / 8, B), 256>>>(n);                              // 7
    k_out<<<dim3(n / 64, B), 128>>>((float*)d_out, n);               // 8
}